// round 14
// baseline (speedup 1.0000x reference)
#include <cuda_runtime.h>
#include <cuda_bf16.h>
#include <math.h>
#include <stdint.h>

#define BATCH 8
#define NPATCH 196
#define LEN_KEEP 147
#define SEQL 148
#define DM 768
#define DI 1536
#define DSTATE 16
#define DTR 48
#define XDBLN 80
#define NLAYERS 12
#define MROWS (BATCH*SEQL)   // 1184

// ---------------- scratch buffers (device globals; no allocation) ----------------
__device__ float g_patches[MROWS*DM];
__device__ int   g_rowpatch[MROWS];
__device__ float g_h[MROWS*DM];
__device__ float2 g_stats[MROWS];
__device__ float g_xz[MROWS*2*DI];
__device__ float g_xc[MROWS*DI];
__device__ float g_xdbl[MROWS*XDBLN];
__device__ float g_dt[MROWS*DI];
__device__ float g_y[MROWS*DI];

// ================= low-level helpers =================
__device__ __forceinline__ uint32_t smem_u32(const void* p) {
    uint32_t a;
    asm("{ .reg .u64 t; cvta.to.shared.u64 t, %1; cvt.u32.u64 %0, t; }" : "=r"(a) : "l"(p));
    return a;
}
__device__ __forceinline__ void ldsm4(uint32_t* r, uint32_t addr) {
    asm volatile("ldmatrix.sync.aligned.m8n8.x4.shared.b16 {%0,%1,%2,%3}, [%4];"
                 : "=r"(r[0]), "=r"(r[1]), "=r"(r[2]), "=r"(r[3]) : "r"(addr));
}
__device__ __forceinline__ void mma16816(float* d, const uint32_t* a, const uint32_t* b) {
    asm volatile("mma.sync.aligned.m16n8k16.row.col.f32.bf16.bf16.f32 "
                 "{%0,%1,%2,%3}, {%4,%5,%6,%7}, {%8,%9}, {%0,%1,%2,%3};"
                 : "+f"(d[0]), "+f"(d[1]), "+f"(d[2]), "+f"(d[3])
                 : "r"(a[0]), "r"(a[1]), "r"(a[2]), "r"(a[3]), "r"(b[0]), "r"(b[1]));
}

// ======== bf16x3 tensor GEMM: C[M,N] (+)= A[M,lda] * W[N,ldb]^T over K-slice ======
// 128x128 CTA tile, 8 warps (2x4), 64x32 warp tile, 16-float K stages (hi|lo bf16).
// EPI: 0 = plain store, 1 = atomicAdd accumulate (for split-K residual add)
// LNA: 1 = apply layernorm affine to A during staging: a=(h-mu)*rstd*w+b
template<int EPI, int LNA>
__global__ __launch_bounds__(256, 2)
void mma_bf16x3(const float* __restrict__ A, const float* __restrict__ W,
                float* __restrict__ C, int M, int N, int lda, int ldb, int Klen,
                const float2* __restrict__ stats,
                const float* __restrict__ lnw, const float* __restrict__ lnb) {
    constexpr int PITCH = 40;                 // bf16 elems per row: [hi 16 | lo 16 | pad 8]
    constexpr int ROWB  = PITCH * 2;          // 80 bytes
    constexpr int STAGEB = 128 * ROWB;        // bytes per stage buffer
    __shared__ __align__(16) __nv_bfloat16 As[2][128][PITCH];
    __shared__ __align__(16) __nv_bfloat16 Bs[2][128][PITCH];

    const int tid  = threadIdx.x;
    const int lane = tid & 31;
    const int wid  = tid >> 5;
    const int wm   = wid & 1;                 // 2 warps along M
    const int wn   = wid >> 1;                // 4 warps along N
    const int m0   = blockIdx.x * 128;
    const int n0   = blockIdx.y * 128;
    const int koff = blockIdx.z * Klen;

    float acc[4][4][4];
    #pragma unroll
    for (int i = 0; i < 4; i++)
        #pragma unroll
        for (int j = 0; j < 4; j++)
            #pragma unroll
            for (int q = 0; q < 4; q++) acc[i][j][q] = 0.0f;

    // conflict-free staging mapping
    const int lrow = (tid & 7) | (((tid >> 4) & 1) << 3) | ((tid >> 5) << 4);
    const int lkc  = ((tid >> 3) & 1) * 8;    // k-chunk: floats 0-7 or 8-15
    const int gmA  = m0 + lrow;
    const bool mok = (gmA < M);
    const float* aPtr = A + (size_t)gmA * lda + koff + lkc;
    const float* bPtr = W + (size_t)(n0 + lrow) * ldb + koff + lkc;

    float2 st = make_float2(0.0f, 0.0f);
    if (LNA && mok) st = stats[gmA];

    const uint32_t aAddr = smem_u32(&As[0][wm*64 + (lane & 15)][0]) + ((lane >> 4) * 16);
    const uint32_t bAddr = smem_u32(&Bs[0][wn*32 + ((lane >> 4) << 3) + (lane & 7)][0])
                         + (((lane >> 3) & 1) * 16);

    const int KT = Klen / 16;

    // apply per-row LN affine to 8 staged A elements (col = global k index of f[0])
    auto ln_apply = [&](float4& v0, float4& v1, int col) {
        float4 w0 = *(const float4*)&lnw[col];
        float4 w1 = *(const float4*)&lnw[col + 4];
        float4 b0 = *(const float4*)&lnb[col];
        float4 b1 = *(const float4*)&lnb[col + 4];
        v0.x = (v0.x - st.x) * st.y * w0.x + b0.x;
        v0.y = (v0.y - st.x) * st.y * w0.y + b0.y;
        v0.z = (v0.z - st.x) * st.y * w0.z + b0.z;
        v0.w = (v0.w - st.x) * st.y * w0.w + b0.w;
        v1.x = (v1.x - st.x) * st.y * w1.x + b1.x;
        v1.y = (v1.y - st.x) * st.y * w1.y + b1.y;
        v1.z = (v1.z - st.x) * st.y * w1.z + b1.z;
        v1.w = (v1.w - st.x) * st.y * w1.w + b1.w;
    };

    // split-store: 8 floats -> hi bf16 16B chunk + lo bf16 16B chunk
    auto split_sts = [&](__nv_bfloat16 (*S)[PITCH], float4 v0, float4 v1) {
        float f[8] = {v0.x, v0.y, v0.z, v0.w, v1.x, v1.y, v1.z, v1.w};
        uint4 hi4, lo4;
        uint32_t* hp = (uint32_t*)&hi4;
        uint32_t* lp = (uint32_t*)&lo4;
        #pragma unroll
        for (int q = 0; q < 4; q++) {
            float x = f[2*q], y = f[2*q+1];
            __nv_bfloat162 h2 = __floats2bfloat162_rn(x, y);
            float2 hf = __bfloat1622float2(h2);
            __nv_bfloat162 l2 = __floats2bfloat162_rn(x - hf.x, y - hf.y);
            hp[q] = *(uint32_t*)&h2;
            lp[q] = *(uint32_t*)&l2;
        }
        *(uint4*)&S[lrow][lkc]      = hi4;
        *(uint4*)&S[lrow][16 + lkc] = lo4;
    };

    // ---- stage 0 ----
    {
        float4 va0 = make_float4(0,0,0,0), va1 = va0;
        if (mok) {
            va0 = *(const float4*)aPtr; va1 = *(const float4*)(aPtr + 4);
            if (LNA) ln_apply(va0, va1, koff + lkc);
        }
        float4 vb0 = *(const float4*)bPtr, vb1 = *(const float4*)(bPtr + 4);
        split_sts(As[0], va0, va1);
        split_sts(Bs[0], vb0, vb1);
    }
    __syncthreads();

    int s = 0;
    for (int kt = 0; kt < KT; kt++) {
        float4 va0, va1, vb0, vb1;
        if (kt + 1 < KT) {
            int k0 = (kt + 1) * 16;
            va0 = make_float4(0,0,0,0); va1 = va0;
            if (mok) {
                va0 = *(const float4*)(aPtr + k0); va1 = *(const float4*)(aPtr + k0 + 4);
                if (LNA) ln_apply(va0, va1, koff + k0 + lkc);
            }
            vb0 = *(const float4*)(bPtr + k0); vb1 = *(const float4*)(bPtr + k0 + 4);
        }

        // ---- compute stage s: acc += Ah*Bh + Ah*Bl + Al*Bh ----
        {
            const uint32_t aS = aAddr + s * STAGEB;
            const uint32_t bS = bAddr + s * STAGEB;
            uint32_t Af[4][4], Bh[4][2], Bl[4][2], t[4];

            #pragma unroll
            for (int mf = 0; mf < 4; mf++) ldsm4(Af[mf], aS + mf * 16 * ROWB);     // A hi
            ldsm4(t, bS);                 Bh[0][0]=t[0]; Bh[0][1]=t[1]; Bh[1][0]=t[2]; Bh[1][1]=t[3];
            ldsm4(t, bS + 16 * ROWB);     Bh[2][0]=t[0]; Bh[2][1]=t[1]; Bh[3][0]=t[2]; Bh[3][1]=t[3];
            #pragma unroll
            for (int mf = 0; mf < 4; mf++)
                #pragma unroll
                for (int nf = 0; nf < 4; nf++) mma16816(acc[mf][nf], Af[mf], Bh[nf]);

            ldsm4(t, bS + 32);            Bl[0][0]=t[0]; Bl[0][1]=t[1]; Bl[1][0]=t[2]; Bl[1][1]=t[3];
            ldsm4(t, bS + 16*ROWB + 32);  Bl[2][0]=t[0]; Bl[2][1]=t[1]; Bl[3][0]=t[2]; Bl[3][1]=t[3];
            #pragma unroll
            for (int mf = 0; mf < 4; mf++)
                #pragma unroll
                for (int nf = 0; nf < 4; nf++) mma16816(acc[mf][nf], Af[mf], Bl[nf]);

            #pragma unroll
            for (int mf = 0; mf < 4; mf++) ldsm4(Af[mf], aS + mf * 16 * ROWB + 32); // A lo
            #pragma unroll
            for (int mf = 0; mf < 4; mf++)
                #pragma unroll
                for (int nf = 0; nf < 4; nf++) mma16816(acc[mf][nf], Af[mf], Bh[nf]);
        }

        if (kt + 1 < KT) {
            int sn = s ^ 1;
            split_sts(As[sn], va0, va1);
            split_sts(Bs[sn], vb0, vb1);
            __syncthreads();
            s = sn;
        }
    }

    // ---- epilogue ----
    #pragma unroll
    for (int mf = 0; mf < 4; mf++) {
        int r0 = m0 + wm*64 + mf*16 + (lane >> 2);
        #pragma unroll
        for (int nf = 0; nf < 4; nf++) {
            int c = n0 + wn*32 + nf*8 + (lane & 3)*2;
            if (EPI == 0) {
                if (r0 < M)     *(float2*)&C[(size_t)r0 * N + c]     = make_float2(acc[mf][nf][0], acc[mf][nf][1]);
                if (r0 + 8 < M) *(float2*)&C[(size_t)(r0+8) * N + c] = make_float2(acc[mf][nf][2], acc[mf][nf][3]);
            } else {
                if (r0 < M) {
                    atomicAdd(&C[(size_t)r0 * N + c],     acc[mf][nf][0]);
                    atomicAdd(&C[(size_t)r0 * N + c + 1], acc[mf][nf][1]);
                }
                if (r0 + 8 < M) {
                    atomicAdd(&C[(size_t)(r0+8) * N + c],     acc[mf][nf][2]);
                    atomicAdd(&C[(size_t)(r0+8) * N + c + 1], acc[mf][nf][3]);
                }
            }
        }
    }
}

// ---------------- packed f32x2 helpers (FFMA2 kernels) ----------------------------
__device__ __forceinline__ void ffma2(unsigned long long& acc,
                                      unsigned long long a, unsigned long long b) {
    asm("fma.rn.f32x2 %0, %1, %2, %0;" : "+l"(acc) : "l"(a), "l"(b));
}
__device__ __forceinline__ unsigned long long pack2(float x, float y) {
    unsigned long long r;
    asm("mov.b64 %0, {%1, %2};" : "=l"(r) : "f"(x), "f"(y));
    return r;
}
__device__ __forceinline__ float2 unpack2(unsigned long long v) {
    float2 f;
    asm("mov.b64 {%0, %1}, %2;" : "=f"(f.x), "=f"(f.y) : "l"(v));
    return f;
}

// -------- fused masking + gather: every block recomputes ranks from noise --------
__global__ void maskgather_kernel(const float* __restrict__ noise,
                                  const float* __restrict__ pix,
                                  float* __restrict__ out_mask,
                                  float* __restrict__ out_ids) {
    __shared__ float s[NPATCH];
    __shared__ int p_sel;
    int m = blockIdx.x;
    int t = m % SEQL, b = m / SEQL;
    int tid = threadIdx.x;
    if (tid < NPATCH) s[tid] = noise[b*NPATCH + tid];
    __syncthreads();
    int rank = -1;
    if (tid < NPATCH) {
        float v = s[tid];
        rank = 0;
        #pragma unroll 4
        for (int j = 0; j < NPATCH; j++) {
            float u = s[j];
            rank += (u < v) || (u == v && j < tid);
        }
    }
    if (t == 0) {
        if (tid < NPATCH) {
            out_mask[b*NPATCH + tid] = (rank >= LEN_KEEP) ? 1.0f : 0.0f;
            out_ids [b*NPATCH + tid] = (float)rank;
        }
        if (tid == 0) g_rowpatch[m] = -1;
        for (int k = tid; k < DM; k += blockDim.x) g_patches[m*DM + k] = 0.0f;
        return;
    }
    if (rank == t - 1) p_sel = tid;      // exactly one thread matches
    __syncthreads();
    int p = p_sel;
    if (tid == 0) g_rowpatch[m] = p;
    int pi = p / 14, pj = p % 14;
    for (int k = tid; k < DM; k += blockDim.x) {
        int c = k >> 8, rem = k & 255, r = rem >> 4, cc = rem & 15;
        g_patches[m*DM + k] =
            pix[((size_t)(b*3 + c)*224 + pi*16 + r)*224 + pj*16 + cc];
    }
}

// =============== FFMA2 SGEMM (patch-embed and dt) =================================
// EPI: 1 patch-embed | 2 softplus(+dt_bias)
template<int EPI>
__global__ __launch_bounds__(256)
void sgemm3(const float* __restrict__ A, const float* __restrict__ W,
            float* __restrict__ C, int M, int N, int K, int lda, int Klen,
            const float* __restrict__ ep0, const float* __restrict__ ep1,
            const float* __restrict__ ep2, const int* __restrict__ rowinfo) {
    constexpr int BM = 64, BN = 64, BK = 16;
    constexpr int PA = 132;
    constexpr int PB = 68;
    __shared__ __align__(16) float As2[2][BK][PA];
    __shared__ __align__(16) float Bs [2][BK][PB];
    const int tid = threadIdx.x;
    const int m0 = blockIdx.x * BM;
    const int n0 = blockIdx.y * BN;
    const int koff = blockIdx.z * Klen;
    const int tx = tid & 15;
    const int ty = tid >> 4;
    unsigned long long acc[4][2];
    #pragma unroll
    for (int i = 0; i < 4; i++) { acc[i][0] = 0ull; acc[i][1] = 0ull; }
    const int KT = Klen / BK;
    const int li = tid >> 4, lj = tid & 15;
    #pragma unroll
    for (int r = 0; r < 4; r++) {
        int i = li + r*16;
        int gm = m0 + i;
        float va = (gm < M) ? A[(size_t)gm * lda + koff + lj] : 0.0f;
        *(unsigned long long*)&As2[0][lj][2*i] = pack2(va, va);
        Bs[0][lj][i] = W[(size_t)(n0 + i) * K + koff + lj];
    }
    __syncthreads();
    int s = 0;
    for (int kt = 0; kt < KT; kt++) {
        float ra[4], rb[4];
        if (kt + 1 < KT) {
            int k0 = koff + (kt + 1) * BK;
            #pragma unroll
            for (int r = 0; r < 4; r++) {
                int i = li + r*16;
                int gm = m0 + i;
                ra[r] = (gm < M) ? A[(size_t)gm * lda + k0 + lj] : 0.0f;
                rb[r] = W[(size_t)(n0 + i) * K + k0 + lj];
            }
        }
        #pragma unroll
        for (int kk = 0; kk < BK; kk++) {
            ulonglong2 a01 = *(const ulonglong2*)&As2[s][kk][ty*8];
            ulonglong2 a23 = *(const ulonglong2*)&As2[s][kk][ty*8 + 4];
            ulonglong2 bq  = *(const ulonglong2*)&Bs [s][kk][tx*4];
            ffma2(acc[0][0], a01.x, bq.x); ffma2(acc[0][1], a01.x, bq.y);
            ffma2(acc[1][0], a01.y, bq.x); ffma2(acc[1][1], a01.y, bq.y);
            ffma2(acc[2][0], a23.x, bq.x); ffma2(acc[2][1], a23.x, bq.y);
            ffma2(acc[3][0], a23.y, bq.x); ffma2(acc[3][1], a23.y, bq.y);
        }
        if (kt + 1 < KT) {
            int sn = s ^ 1;
            #pragma unroll
            for (int r = 0; r < 4; r++) {
                int i = li + r*16;
                *(unsigned long long*)&As2[sn][lj][2*i] = pack2(ra[r], ra[r]);
                Bs[sn][lj][i] = rb[r];
            }
            __syncthreads();
            s = sn;
        }
    }
    #pragma unroll
    for (int i = 0; i < 4; i++) {
        int m = m0 + ty*4 + i;
        if (m >= M) continue;
        int rp = 0;
        if (EPI == 1) rp = rowinfo[m];
        #pragma unroll
        for (int j = 0; j < 2; j++) {
            float2 v2 = unpack2(acc[i][j]);
            int n = n0 + tx*4 + j*2;
            if (EPI == 2) {
                float x0 = v2.x + ep0[n],   x1 = v2.y + ep0[n+1];
                v2.x = (x0 > 20.0f) ? x0 : log1pf(__expf(x0));
                v2.y = (x1 > 20.0f) ? x1 : log1pf(__expf(x1));
                *(float2*)&C[(size_t)m * N + n] = v2;
            } else { // EPI == 1
                float vv[2] = {v2.x, v2.y};
                #pragma unroll
                for (int q = 0; q < 2; q++) {
                    int nn = n + q;
                    float v = vv[q];
                    if (rp < 0) v = ep1[nn] + ep2[nn];
                    else        v = v + ep0[nn] + ep2[(size_t)(1+rp)*DM + nn];
                    C[(size_t)m * N + nn] = v;
                }
            }
        }
    }
}

// ---------------- small SGEMM for x_dbl (N=80), split-K with atomicAdd ------------
template<int BM, int BN, int BK, int TM, int TN>
__global__ __launch_bounds__(256)
void sgemm_small(const float* __restrict__ A, const float* __restrict__ W,
                 float* __restrict__ C, int M, int N, int K, int lda, int Klen) {
    __shared__ float As[BK][BM + 4];
    __shared__ float Bs[BK][BN + 4];
    const int tid = threadIdx.x;
    const int m0 = blockIdx.x * BM;
    const int n0 = blockIdx.y * BN;
    const int koff = blockIdx.z * Klen;
    constexpr int CT = BN / TN;
    const int tx = tid % CT;
    const int ty = tid / CT;
    float acc[TM][TN];
    #pragma unroll
    for (int i = 0; i < TM; i++)
        #pragma unroll
        for (int j = 0; j < TN; j++) acc[i][j] = 0.0f;
    constexpr int AREP = (BM * BK) / 256;
    constexpr int BREP = (BN * BK + 255) / 256;
    for (int k0 = koff; k0 < koff + Klen; k0 += BK) {
        #pragma unroll
        for (int r = 0; r < AREP; r++) {
            int idx = tid + r * 256;
            int i = idx / BK, j = idx % BK;
            int gm = m0 + i;
            As[j][i] = (gm < M) ? A[(size_t)gm * lda + k0 + j] : 0.0f;
        }
        #pragma unroll
        for (int r = 0; r < BREP; r++) {
            int idx = tid + r * 256;
            if (idx < BN * BK) {
                int i = idx / BK, j = idx % BK;
                Bs[j][i] = W[(size_t)(n0 + i) * K + k0 + j];
            }
        }
        __syncthreads();
        #pragma unroll
        for (int kk = 0; kk < BK; kk++) {
            float a[TM], bb[TN];
            #pragma unroll
            for (int i = 0; i < TM; i++) a[i] = As[kk][ty*TM + i];
            #pragma unroll
            for (int j = 0; j < TN; j++) bb[j] = Bs[kk][tx*TN + j];
            #pragma unroll
            for (int i = 0; i < TM; i++)
                #pragma unroll
                for (int j = 0; j < TN; j++)
                    acc[i][j] = fmaf(a[i], bb[j], acc[i][j]);
        }
        __syncthreads();
    }
    #pragma unroll
    for (int i = 0; i < TM; i++) {
        int m = m0 + ty*TM + i;
        if (m >= M) continue;
        #pragma unroll
        for (int j = 0; j < TN; j++) {
            int n = n0 + tx*TN + j;
            atomicAdd(&C[(size_t)m * N + n], acc[i][j]);
        }
    }
}

// ------- depthwise causal conv1d (k=4) + SiLU, float2 vectorized; zeroes xdbl ----
__global__ void conv_silu_kernel(const float* __restrict__ cw,
                                 const float* __restrict__ cb) {
    int m = blockIdx.x;
    int t = m % SEQL, b = m / SEQL;
    if (threadIdx.x < XDBLN) g_xdbl[(size_t)m*XDBLN + threadIdx.x] = 0.0f;
    for (int d2 = threadIdx.x; d2 < DI/2; d2 += blockDim.x) {
        int d = d2 * 2;
        float4 wA = *(const float4*)&cw[d*4];
        float4 wB = *(const float4*)&cw[d*4 + 4];
        float2 s = *(const float2*)&cb[d];
        const float* base = g_xz + (size_t)(b*SEQL) * (2*DI) + d;
        if (t >= 3) { float2 v = *(const float2*)&base[(size_t)(t-3)*(2*DI)];
                      s.x = fmaf(wA.x, v.x, s.x); s.y = fmaf(wB.x, v.y, s.y); }
        if (t >= 2) { float2 v = *(const float2*)&base[(size_t)(t-2)*(2*DI)];
                      s.x = fmaf(wA.y, v.x, s.x); s.y = fmaf(wB.y, v.y, s.y); }
        if (t >= 1) { float2 v = *(const float2*)&base[(size_t)(t-1)*(2*DI)];
                      s.x = fmaf(wA.z, v.x, s.x); s.y = fmaf(wB.z, v.y, s.y); }
        { float2 v = *(const float2*)&base[(size_t)t*(2*DI)];
          s.x = fmaf(wA.w, v.x, s.x); s.y = fmaf(wB.w, v.y, s.y); }
        float2 o;
        o.x = s.x / (1.0f + __expf(-s.x));
        o.y = s.y / (1.0f + __expf(-s.y));
        *(float2*)&g_xc[(size_t)m*DI + d] = o;
    }
}

// ---------------- layernorm reductions -------------------------------------------
__device__ __forceinline__ float block_reduce_sum_256(float v, float* sh, float* bc) {
    #pragma unroll
    for (int o = 16; o > 0; o >>= 1) v += __shfl_xor_sync(0xffffffffu, v, o);
    int w = threadIdx.x >> 5;
    if ((threadIdx.x & 31) == 0) sh[w] = v;
    __syncthreads();
    if (threadIdx.x == 0) {
        float s = 0.0f;
        #pragma unroll
        for (int i = 0; i < 8; i++) s += sh[i];
        *bc = s;
    }
    __syncthreads();
    return *bc;
}

// stats-only LN: writes (mean, rstd) per row for staging-fused normalization
__global__ void ln_stats_kernel(const float* __restrict__ x, float2* __restrict__ stats) {
    __shared__ float sh[8];
    __shared__ float bc;
    int m = blockIdx.x, tid = threadIdx.x;
    const float* xr = x + (size_t)m * DM;
    float v0 = xr[tid], v1 = xr[tid + 256], v2 = xr[tid + 512];
    float mean = block_reduce_sum_256(v0 + v1 + v2, sh, &bc) * (1.0f / DM);
    float d0 = v0 - mean, d1 = v1 - mean, d2 = v2 - mean;
    __syncthreads();
    float var = block_reduce_sum_256(d0*d0 + d1*d1 + d2*d2, sh, &bc) * (1.0f / DM);
    if (tid == 0) stats[m] = make_float2(mean, rsqrtf(var + 1e-12f));
}

// full LN (final layer only)
__global__ void ln_kernel(const float* __restrict__ x, const float* __restrict__ w,
                          const float* __restrict__ bias, float* __restrict__ out) {
    __shared__ float sh[8];
    __shared__ float bc;
    int m = blockIdx.x, tid = threadIdx.x;
    const float* xr = x + (size_t)m * DM;
    float v0 = xr[tid], v1 = xr[tid + 256], v2 = xr[tid + 512];
    float mean = block_reduce_sum_256(v0 + v1 + v2, sh, &bc) * (1.0f / DM);
    float d0 = v0 - mean, d1 = v1 - mean, d2 = v2 - mean;
    __syncthreads();
    float var = block_reduce_sum_256(d0*d0 + d1*d1 + d2*d2, sh, &bc) * (1.0f / DM);
    float inv = rsqrtf(var + 1e-12f);
    float* o = out + (size_t)m * DM;
    o[tid]       = d0 * inv * w[tid]       + bias[tid];
    o[tid + 256] = d1 * inv * w[tid + 256] + bias[tid + 256];
    o[tid + 512] = d2 * inv * w[tid + 512] + bias[tid + 512];
}

// ---------------- selective scan: 16 lanes/channel, prefetched loads --------------
__global__ void scan_kernel(const float* __restrict__ A_log_l,
                            const float* __restrict__ Dp_l) {
    int lane = threadIdx.x & 31;
    int warp = threadIdx.x >> 5;
    int widx = blockIdx.x * 8 + warp;
    int ch = widx * 2 + (lane >> 4);       // 2 channels per warp
    int b = ch / DI, d = ch % DI;
    int n = lane & 15;
    float Av = -__expf(A_log_l[d*DSTATE + n]);
    float Dv = Dp_l[d];
    float h = 0.0f;
    int base = b * SEQL;
    float dt = g_dt[(size_t)base*DI + d];
    float xc = g_xc[(size_t)base*DI + d];
    float Bn = g_xdbl[(size_t)base*XDBLN + DTR + n];
    float Cn = g_xdbl[(size_t)base*XDBLN + DTR + DSTATE + n];
    for (int t = 0; t < SEQL; t++) {
        float dtN, xcN, BnN, CnN;
        if (t + 1 < SEQL) {
            int m1 = base + t + 1;
            dtN = g_dt[(size_t)m1*DI + d];
            xcN = g_xc[(size_t)m1*DI + d];
            BnN = g_xdbl[(size_t)m1*XDBLN + DTR + n];
            CnN = g_xdbl[(size_t)m1*XDBLN + DTR + DSTATE + n];
        }
        float dA = __expf(dt * Av);
        h = fmaf(dA, h, (dt * xc) * Bn);
        float p = h * Cn;
        p += __shfl_xor_sync(0xffffffffu, p, 8);
        p += __shfl_xor_sync(0xffffffffu, p, 4);
        p += __shfl_xor_sync(0xffffffffu, p, 2);
        p += __shfl_xor_sync(0xffffffffu, p, 1);
        if (n == 0) {
            int m = base + t;
            float z = g_xz[(size_t)m*(2*DI) + DI + d];
            float y = (p + xc * Dv) * (z / (1.0f + __expf(-z)));
            g_y[(size_t)m*DI + d] = y;
        }
        dt = dtN; xc = xcN; Bn = BnN; Cn = CnN;
    }
}

// ---------------- host launcher ---------------------------------------------------
extern "C" void kernel_launch(void* const* d_in, const int* in_sizes, int n_in,
                              void* d_out, int out_size) {
    const float* pixel     = (const float*)d_in[0];
    const float* noise     = (const float*)d_in[1];
    const float* conv_w    = (const float*)d_in[2];
    const float* conv_b    = (const float*)d_in[3];
    const float* cls_token = (const float*)d_in[4];
    const float* pos_embed = (const float*)d_in[5];
    const float* ln_w      = (const float*)d_in[6];
    const float* ln_b      = (const float*)d_in[7];
    const float* W_in      = (const float*)d_in[8];
    const float* conv1d_w  = (const float*)d_in[9];
    const float* conv1d_b  = (const float*)d_in[10];
    const float* W_x       = (const float*)d_in[11];
    const float* W_dt      = (const float*)d_in[12];
    const float* dt_bias   = (const float*)d_in[13];
    const float* A_log     = (const float*)d_in[14];
    const float* Dp        = (const float*)d_in[15];
    const float* W_out     = (const float*)d_in[16];
    const float* lnf_w     = (const float*)d_in[17];
    const float* lnf_b     = (const float*)d_in[18];

    float* out      = (float*)d_out;
    float* out_h    = out;                       // (8,148,768)
    float* out_mask = out + (size_t)MROWS*DM;    // (8,196)
    float* out_ids  = out_mask + BATCH*NPATCH;   // (8,196) as float

    float *p_patches, *p_h, *p_xz, *p_xc, *p_xdbl, *p_dt, *p_y;
    float2 *p_stats;
    int *p_rowpatch;
    cudaGetSymbolAddress((void**)&p_patches, g_patches);
    cudaGetSymbolAddress((void**)&p_h,       g_h);
    cudaGetSymbolAddress((void**)&p_stats,   g_stats);
    cudaGetSymbolAddress((void**)&p_xz,      g_xz);
    cudaGetSymbolAddress((void**)&p_xc,      g_xc);
    cudaGetSymbolAddress((void**)&p_xdbl,    g_xdbl);
    cudaGetSymbolAddress((void**)&p_dt,      g_dt);
    cudaGetSymbolAddress((void**)&p_y,       g_y);
    cudaGetSymbolAddress((void**)&p_rowpatch, g_rowpatch);

    const int MB64  = (MROWS + 63) / 64;     // 19
    const int MB128 = (MROWS + 127) / 128;   // 10

    // fused masking + patch gather (launch #1), then patch-embed GEMM (#2)
    maskgather_kernel<<<MROWS, 256>>>(noise, pixel, out_mask, out_ids);
    sgemm3<1><<<dim3(MB64, DM/64, 1), 256>>>(p_patches, conv_w, p_h,
        MROWS, DM, DM, DM, DM, conv_b, cls_token, pos_embed, p_rowpatch);

    for (int l = 0; l < NLAYERS; l++) {
        const float* Wi  = W_in     + (size_t)l * (2*DI) * DM;
        const float* cw  = conv1d_w + (size_t)l * DI * 4;
        const float* cb  = conv1d_b + (size_t)l * DI;
        const float* Wx  = W_x      + (size_t)l * XDBLN * DI;
        const float* Wd  = W_dt     + (size_t)l * DI * DTR;
        const float* db  = dt_bias  + (size_t)l * DI;
        const float* Al  = A_log    + (size_t)l * DI * DSTATE;
        const float* Dl  = Dp       + (size_t)l * DI;
        const float* Wo  = W_out    + (size_t)l * DM * DI;

        // LN stats only (#3 in layer 0)
        ln_stats_kernel<<<MROWS, 256>>>(p_h, p_stats);

        // (#4, profiled) xz = LN(h) @ W_in^T — bf16x3 tensor GEMM, LN in staging
        mma_bf16x3<0,1><<<dim3(MB128, (2*DI)/128), 256>>>(
            p_h, Wi, p_xz, MROWS, 2*DI, DM, DM, DM,
            p_stats, ln_w + l*DM, ln_b + l*DM);

        // depthwise causal conv + silu (also zero-inits xdbl rows)
        conv_silu_kernel<<<MROWS, 256>>>(cw, cb);

        // x_dbl = xc @ W_x^T  (1184 x 80, K=1536) — split-K=4 atomic
        sgemm_small<64,16,16,2,2><<<dim3(MB64, XDBLN/16, 4), 256>>>(
            p_xc, Wx, p_xdbl, MROWS, XDBLN, DI, DI, DI/4);

        // dt = softplus(x_dbl[:, :48] @ W_dt^T + dt_bias)
        sgemm3<2><<<dim3(MB64, DI/64, 1), 256>>>(p_xdbl, Wd, p_dt,
            MROWS, DI, DTR, XDBLN, DTR, db, nullptr, nullptr, nullptr);

        // selective scan + D skip + gate
        scan_kernel<<<(BATCH*DI)/16, 256>>>(Al, Dl);

        // h += y @ W_out^T — bf16x3 split-K=4 (240 CTAs), atomicAdd
        mma_bf16x3<1,0><<<dim3(MB128, DM/128, 4), 256>>>(
            p_y, Wo, p_h, MROWS, DM, DI, DI, DI/4,
            nullptr, nullptr, nullptr);
    }

    // final layernorm straight into the output buffer
    ln_kernel<<<MROWS, 256>>>(p_h, lnf_w, lnf_b, out_h);
}

// round 15
// speedup vs baseline: 1.0182x; 1.0182x over previous
#include <cuda_runtime.h>
#include <cuda_bf16.h>
#include <math.h>
#include <stdint.h>

#define BATCH 8
#define NPATCH 196
#define LEN_KEEP 147
#define SEQL 148
#define DM 768
#define DI 1536
#define DSTATE 16
#define DTR 48
#define XDBLN 80
#define NLAYERS 12
#define MROWS (BATCH*SEQL)   // 1184

// ---------------- scratch buffers (device globals; no allocation) ----------------
__device__ float g_patches[MROWS*DM];
__device__ int   g_rowpatch[MROWS];
__device__ float g_h[MROWS*DM];
__device__ float g_ln[MROWS*DM];
__device__ float g_xz[MROWS*2*DI];
__device__ float g_xc[MROWS*DI];
__device__ float g_xdbl[MROWS*XDBLN];
__device__ float g_dt[MROWS*DI];
__device__ float g_y[MROWS*DI];

// ================= low-level helpers =================
__device__ __forceinline__ uint32_t smem_u32(const void* p) {
    uint32_t a;
    asm("{ .reg .u64 t; cvta.to.shared.u64 t, %1; cvt.u32.u64 %0, t; }" : "=r"(a) : "l"(p));
    return a;
}
__device__ __forceinline__ void ldsm4(uint32_t* r, uint32_t addr) {
    asm volatile("ldmatrix.sync.aligned.m8n8.x4.shared.b16 {%0,%1,%2,%3}, [%4];"
                 : "=r"(r[0]), "=r"(r[1]), "=r"(r[2]), "=r"(r[3]) : "r"(addr));
}
__device__ __forceinline__ void mma16816(float* d, const uint32_t* a, const uint32_t* b) {
    asm volatile("mma.sync.aligned.m16n8k16.row.col.f32.bf16.bf16.f32 "
                 "{%0,%1,%2,%3}, {%4,%5,%6,%7}, {%8,%9}, {%0,%1,%2,%3};"
                 : "+f"(d[0]), "+f"(d[1]), "+f"(d[2]), "+f"(d[3])
                 : "r"(a[0]), "r"(a[1]), "r"(a[2]), "r"(a[3]), "r"(b[0]), "r"(b[1]));
}
// vector fp32 reduction (sm_90+ base ISA; halves REDG issue count)
__device__ __forceinline__ void red_add_v2(float* ptr, float x, float y) {
    asm volatile("red.global.add.v2.f32 [%0], {%1, %2};"
                 :: "l"(ptr), "f"(x), "f"(y) : "memory");
}

// ======== bf16x3 tensor GEMM: C[M,N] (+)= A[M,lda] * W[N,ldb]^T over K-slice ======
// 128x128 CTA tile, 8 warps (2x4), 64x32 warp tile, 16-float K stages (hi|lo bf16).
// EPI: 0 = plain store, 1 = vector-RED accumulate (for split-K residual add)
template<int EPI>
__global__ __launch_bounds__(256, 2)
void mma_bf16x3(const float* __restrict__ A, const float* __restrict__ W,
                float* __restrict__ C, int M, int N, int lda, int ldb, int Klen) {
    constexpr int PITCH = 40;                 // bf16 elems per row: [hi 16 | lo 16 | pad 8]
    constexpr int ROWB  = PITCH * 2;          // 80 bytes
    constexpr int STAGEB = 128 * ROWB;        // bytes per stage buffer
    __shared__ __align__(16) __nv_bfloat16 As[2][128][PITCH];
    __shared__ __align__(16) __nv_bfloat16 Bs[2][128][PITCH];

    const int tid  = threadIdx.x;
    const int lane = tid & 31;
    const int wid  = tid >> 5;
    const int wm   = wid & 1;                 // 2 warps along M
    const int wn   = wid >> 1;                // 4 warps along N
    const int m0   = blockIdx.x * 128;
    const int n0   = blockIdx.y * 128;
    const int koff = blockIdx.z * Klen;

    float acc[4][4][4];
    #pragma unroll
    for (int i = 0; i < 4; i++)
        #pragma unroll
        for (int j = 0; j < 4; j++)
            #pragma unroll
            for (int q = 0; q < 4; q++) acc[i][j][q] = 0.0f;

    // conflict-free staging mapping
    const int lrow = (tid & 7) | (((tid >> 4) & 1) << 3) | ((tid >> 5) << 4);
    const int lkc  = ((tid >> 3) & 1) * 8;    // k-chunk: floats 0-7 or 8-15
    const int gmA  = m0 + lrow;
    const bool mok = (gmA < M);
    const float* aPtr = A + (size_t)gmA * lda + koff + lkc;
    const float* bPtr = W + (size_t)(n0 + lrow) * ldb + koff + lkc;

    const uint32_t aAddr = smem_u32(&As[0][wm*64 + (lane & 15)][0]) + ((lane >> 4) * 16);
    const uint32_t bAddr = smem_u32(&Bs[0][wn*32 + ((lane >> 4) << 3) + (lane & 7)][0])
                         + (((lane >> 3) & 1) * 16);

    const int KT = Klen / 16;

    // split-store: 8 floats -> hi bf16 16B chunk + lo bf16 16B chunk
    auto split_sts = [&](__nv_bfloat16 (*S)[PITCH], float4 v0, float4 v1) {
        float f[8] = {v0.x, v0.y, v0.z, v0.w, v1.x, v1.y, v1.z, v1.w};
        uint4 hi4, lo4;
        uint32_t* hp = (uint32_t*)&hi4;
        uint32_t* lp = (uint32_t*)&lo4;
        #pragma unroll
        for (int q = 0; q < 4; q++) {
            float x = f[2*q], y = f[2*q+1];
            __nv_bfloat162 h2 = __floats2bfloat162_rn(x, y);
            float2 hf = __bfloat1622float2(h2);
            __nv_bfloat162 l2 = __floats2bfloat162_rn(x - hf.x, y - hf.y);
            hp[q] = *(uint32_t*)&h2;
            lp[q] = *(uint32_t*)&l2;
        }
        *(uint4*)&S[lrow][lkc]      = hi4;
        *(uint4*)&S[lrow][16 + lkc] = lo4;
    };

    // ---- stage 0 ----
    {
        float4 va0 = make_float4(0,0,0,0), va1 = va0;
        if (mok) { va0 = *(const float4*)aPtr; va1 = *(const float4*)(aPtr + 4); }
        float4 vb0 = *(const float4*)bPtr, vb1 = *(const float4*)(bPtr + 4);
        split_sts(As[0], va0, va1);
        split_sts(Bs[0], vb0, vb1);
    }
    __syncthreads();

    int s = 0;
    for (int kt = 0; kt < KT; kt++) {
        float4 va0, va1, vb0, vb1;
        if (kt + 1 < KT) {
            int k0 = (kt + 1) * 16;
            va0 = make_float4(0,0,0,0); va1 = va0;
            if (mok) { va0 = *(const float4*)(aPtr + k0); va1 = *(const float4*)(aPtr + k0 + 4); }
            vb0 = *(const float4*)(bPtr + k0); vb1 = *(const float4*)(bPtr + k0 + 4);
        }

        // ---- compute stage s: acc += Ah*Bh + Ah*Bl + Al*Bh ----
        {
            const uint32_t aS = aAddr + s * STAGEB;
            const uint32_t bS = bAddr + s * STAGEB;
            uint32_t Af[4][4], Bh[4][2], Bl[4][2], t[4];

            #pragma unroll
            for (int mf = 0; mf < 4; mf++) ldsm4(Af[mf], aS + mf * 16 * ROWB);     // A hi
            ldsm4(t, bS);                 Bh[0][0]=t[0]; Bh[0][1]=t[1]; Bh[1][0]=t[2]; Bh[1][1]=t[3];
            ldsm4(t, bS + 16 * ROWB);     Bh[2][0]=t[0]; Bh[2][1]=t[1]; Bh[3][0]=t[2]; Bh[3][1]=t[3];
            #pragma unroll
            for (int mf = 0; mf < 4; mf++)
                #pragma unroll
                for (int nf = 0; nf < 4; nf++) mma16816(acc[mf][nf], Af[mf], Bh[nf]);

            ldsm4(t, bS + 32);            Bl[0][0]=t[0]; Bl[0][1]=t[1]; Bl[1][0]=t[2]; Bl[1][1]=t[3];
            ldsm4(t, bS + 16*ROWB + 32);  Bl[2][0]=t[0]; Bl[2][1]=t[1]; Bl[3][0]=t[2]; Bl[3][1]=t[3];
            #pragma unroll
            for (int mf = 0; mf < 4; mf++)
                #pragma unroll
                for (int nf = 0; nf < 4; nf++) mma16816(acc[mf][nf], Af[mf], Bl[nf]);

            #pragma unroll
            for (int mf = 0; mf < 4; mf++) ldsm4(Af[mf], aS + mf * 16 * ROWB + 32); // A lo
            #pragma unroll
            for (int mf = 0; mf < 4; mf++)
                #pragma unroll
                for (int nf = 0; nf < 4; nf++) mma16816(acc[mf][nf], Af[mf], Bh[nf]);
        }

        if (kt + 1 < KT) {
            int sn = s ^ 1;
            split_sts(As[sn], va0, va1);
            split_sts(Bs[sn], vb0, vb1);
            __syncthreads();
            s = sn;
        }
    }

    // ---- epilogue ----
    #pragma unroll
    for (int mf = 0; mf < 4; mf++) {
        int r0 = m0 + wm*64 + mf*16 + (lane >> 2);
        #pragma unroll
        for (int nf = 0; nf < 4; nf++) {
            int c = n0 + wn*32 + nf*8 + (lane & 3)*2;
            if (EPI == 0) {
                if (r0 < M)     *(float2*)&C[(size_t)r0 * N + c]     = make_float2(acc[mf][nf][0], acc[mf][nf][1]);
                if (r0 + 8 < M) *(float2*)&C[(size_t)(r0+8) * N + c] = make_float2(acc[mf][nf][2], acc[mf][nf][3]);
            } else {
                if (r0 < M)
                    red_add_v2(&C[(size_t)r0 * N + c],     acc[mf][nf][0], acc[mf][nf][1]);
                if (r0 + 8 < M)
                    red_add_v2(&C[(size_t)(r0+8) * N + c], acc[mf][nf][2], acc[mf][nf][3]);
            }
        }
    }
}

// ---------------- packed f32x2 helpers (FFMA2 kernels) ----------------------------
__device__ __forceinline__ void ffma2(unsigned long long& acc,
                                      unsigned long long a, unsigned long long b) {
    asm("fma.rn.f32x2 %0, %1, %2, %0;" : "+l"(acc) : "l"(a), "l"(b));
}
__device__ __forceinline__ unsigned long long pack2(float x, float y) {
    unsigned long long r;
    asm("mov.b64 %0, {%1, %2};" : "=l"(r) : "f"(x), "f"(y));
    return r;
}
__device__ __forceinline__ float2 unpack2(unsigned long long v) {
    float2 f;
    asm("mov.b64 {%0, %1}, %2;" : "=f"(f.x), "=f"(f.y) : "l"(v));
    return f;
}

// -------- fused masking + gather: every block recomputes ranks from noise --------
__global__ void maskgather_kernel(const float* __restrict__ noise,
                                  const float* __restrict__ pix,
                                  float* __restrict__ out_mask,
                                  float* __restrict__ out_ids) {
    __shared__ float s[NPATCH];
    __shared__ int p_sel;
    int m = blockIdx.x;
    int t = m % SEQL, b = m / SEQL;
    int tid = threadIdx.x;
    if (tid < NPATCH) s[tid] = noise[b*NPATCH + tid];
    __syncthreads();
    int rank = -1;
    if (tid < NPATCH) {
        float v = s[tid];
        rank = 0;
        #pragma unroll 4
        for (int j = 0; j < NPATCH; j++) {
            float u = s[j];
            rank += (u < v) || (u == v && j < tid);
        }
    }
    if (t == 0) {
        if (tid < NPATCH) {
            out_mask[b*NPATCH + tid] = (rank >= LEN_KEEP) ? 1.0f : 0.0f;
            out_ids [b*NPATCH + tid] = (float)rank;
        }
        if (tid == 0) g_rowpatch[m] = -1;
        for (int k = tid; k < DM; k += blockDim.x) g_patches[m*DM + k] = 0.0f;
        return;
    }
    if (rank == t - 1) p_sel = tid;      // exactly one thread matches
    __syncthreads();
    int p = p_sel;
    if (tid == 0) g_rowpatch[m] = p;
    int pi = p / 14, pj = p % 14;
    for (int k = tid; k < DM; k += blockDim.x) {
        int c = k >> 8, rem = k & 255, r = rem >> 4, cc = rem & 15;
        g_patches[m*DM + k] =
            pix[((size_t)(b*3 + c)*224 + pi*16 + r)*224 + pj*16 + cc];
    }
}

// =============== FFMA2 SGEMM (patch-embed and dt) =================================
// EPI: 1 patch-embed | 2 softplus(+dt_bias)
template<int EPI>
__global__ __launch_bounds__(256)
void sgemm3(const float* __restrict__ A, const float* __restrict__ W,
            float* __restrict__ C, int M, int N, int K, int lda, int Klen,
            const float* __restrict__ ep0, const float* __restrict__ ep1,
            const float* __restrict__ ep2, const int* __restrict__ rowinfo) {
    constexpr int BM = 64, BN = 64, BK = 16;
    constexpr int PA = 132;
    constexpr int PB = 68;
    __shared__ __align__(16) float As2[2][BK][PA];
    __shared__ __align__(16) float Bs [2][BK][PB];
    const int tid = threadIdx.x;
    const int m0 = blockIdx.x * BM;
    const int n0 = blockIdx.y * BN;
    const int koff = blockIdx.z * Klen;
    const int tx = tid & 15;
    const int ty = tid >> 4;
    unsigned long long acc[4][2];
    #pragma unroll
    for (int i = 0; i < 4; i++) { acc[i][0] = 0ull; acc[i][1] = 0ull; }
    const int KT = Klen / BK;
    const int li = tid >> 4, lj = tid & 15;
    #pragma unroll
    for (int r = 0; r < 4; r++) {
        int i = li + r*16;
        int gm = m0 + i;
        float va = (gm < M) ? A[(size_t)gm * lda + koff + lj] : 0.0f;
        *(unsigned long long*)&As2[0][lj][2*i] = pack2(va, va);
        Bs[0][lj][i] = W[(size_t)(n0 + i) * K + koff + lj];
    }
    __syncthreads();
    int s = 0;
    for (int kt = 0; kt < KT; kt++) {
        float ra[4], rb[4];
        if (kt + 1 < KT) {
            int k0 = koff + (kt + 1) * BK;
            #pragma unroll
            for (int r = 0; r < 4; r++) {
                int i = li + r*16;
                int gm = m0 + i;
                ra[r] = (gm < M) ? A[(size_t)gm * lda + k0 + lj] : 0.0f;
                rb[r] = W[(size_t)(n0 + i) * K + k0 + lj];
            }
        }
        #pragma unroll
        for (int kk = 0; kk < BK; kk++) {
            ulonglong2 a01 = *(const ulonglong2*)&As2[s][kk][ty*8];
            ulonglong2 a23 = *(const ulonglong2*)&As2[s][kk][ty*8 + 4];
            ulonglong2 bq  = *(const ulonglong2*)&Bs [s][kk][tx*4];
            ffma2(acc[0][0], a01.x, bq.x); ffma2(acc[0][1], a01.x, bq.y);
            ffma2(acc[1][0], a01.y, bq.x); ffma2(acc[1][1], a01.y, bq.y);
            ffma2(acc[2][0], a23.x, bq.x); ffma2(acc[2][1], a23.x, bq.y);
            ffma2(acc[3][0], a23.y, bq.x); ffma2(acc[3][1], a23.y, bq.y);
        }
        if (kt + 1 < KT) {
            int sn = s ^ 1;
            #pragma unroll
            for (int r = 0; r < 4; r++) {
                int i = li + r*16;
                *(unsigned long long*)&As2[sn][lj][2*i] = pack2(ra[r], ra[r]);
                Bs[sn][lj][i] = rb[r];
            }
            __syncthreads();
            s = sn;
        }
    }
    #pragma unroll
    for (int i = 0; i < 4; i++) {
        int m = m0 + ty*4 + i;
        if (m >= M) continue;
        int rp = 0;
        if (EPI == 1) rp = rowinfo[m];
        #pragma unroll
        for (int j = 0; j < 2; j++) {
            float2 v2 = unpack2(acc[i][j]);
            int n = n0 + tx*4 + j*2;
            if (EPI == 2) {
                float x0 = v2.x + ep0[n],   x1 = v2.y + ep0[n+1];
                v2.x = (x0 > 20.0f) ? x0 : log1pf(__expf(x0));
                v2.y = (x1 > 20.0f) ? x1 : log1pf(__expf(x1));
                *(float2*)&C[(size_t)m * N + n] = v2;
            } else { // EPI == 1
                float vv[2] = {v2.x, v2.y};
                #pragma unroll
                for (int q = 0; q < 2; q++) {
                    int nn = n + q;
                    float v = vv[q];
                    if (rp < 0) v = ep1[nn] + ep2[nn];
                    else        v = v + ep0[nn] + ep2[(size_t)(1+rp)*DM + nn];
                    C[(size_t)m * N + nn] = v;
                }
            }
        }
    }
}

// ---------------- small SGEMM for x_dbl (N=80), split-K with vector RED -----------
// Thread tile (2,2): 4 LDS per 4 FMA; epilogue = 2 red.add.v2 per thread.
template<int BM, int BN, int BK, int TM, int TN>
__global__ __launch_bounds__(256)
void sgemm_small(const float* __restrict__ A, const float* __restrict__ W,
                 float* __restrict__ C, int M, int N, int K, int lda, int Klen) {
    __shared__ float As[BK][BM + 4];
    __shared__ float Bs[BK][BN + 4];
    const int tid = threadIdx.x;
    const int m0 = blockIdx.x * BM;
    const int n0 = blockIdx.y * BN;
    const int koff = blockIdx.z * Klen;
    constexpr int CT = BN / TN;
    const int tx = tid % CT;
    const int ty = tid / CT;
    float acc[TM][TN];
    #pragma unroll
    for (int i = 0; i < TM; i++)
        #pragma unroll
        for (int j = 0; j < TN; j++) acc[i][j] = 0.0f;
    constexpr int AREP = (BM * BK) / 256;
    constexpr int BREP = (BN * BK + 255) / 256;
    for (int k0 = koff; k0 < koff + Klen; k0 += BK) {
        #pragma unroll
        for (int r = 0; r < AREP; r++) {
            int idx = tid + r * 256;
            int i = idx / BK, j = idx % BK;
            int gm = m0 + i;
            As[j][i] = (gm < M) ? A[(size_t)gm * lda + k0 + j] : 0.0f;
        }
        #pragma unroll
        for (int r = 0; r < BREP; r++) {
            int idx = tid + r * 256;
            if (idx < BN * BK) {
                int i = idx / BK, j = idx % BK;
                Bs[j][i] = W[(size_t)(n0 + i) * K + k0 + j];
            }
        }
        __syncthreads();
        #pragma unroll
        for (int kk = 0; kk < BK; kk++) {
            float a[TM], bb[TN];
            #pragma unroll
            for (int i = 0; i < TM; i++) a[i] = As[kk][ty*TM + i];
            #pragma unroll
            for (int j = 0; j < TN; j++) bb[j] = Bs[kk][tx*TN + j];
            #pragma unroll
            for (int i = 0; i < TM; i++)
                #pragma unroll
                for (int j = 0; j < TN; j++)
                    acc[i][j] = fmaf(a[i], bb[j], acc[i][j]);
        }
        __syncthreads();
    }
    #pragma unroll
    for (int i = 0; i < TM; i++) {
        int m = m0 + ty*TM + i;
        if (m >= M) continue;
        // TN == 2 and tx*TN is even -> 8B-aligned pair
        red_add_v2(&C[(size_t)m * N + n0 + tx*TN], acc[i][0], acc[i][1]);
    }
}

// ------- depthwise causal conv1d (k=4) + SiLU, float2 vectorized; zeroes xdbl ----
__global__ void conv_silu_kernel(const float* __restrict__ cw,
                                 const float* __restrict__ cb) {
    int m = blockIdx.x;
    int t = m % SEQL, b = m / SEQL;
    if (threadIdx.x < XDBLN) g_xdbl[(size_t)m*XDBLN + threadIdx.x] = 0.0f;
    for (int d2 = threadIdx.x; d2 < DI/2; d2 += blockDim.x) {
        int d = d2 * 2;
        float4 wA = *(const float4*)&cw[d*4];
        float4 wB = *(const float4*)&cw[d*4 + 4];
        float2 s = *(const float2*)&cb[d];
        const float* base = g_xz + (size_t)(b*SEQL) * (2*DI) + d;
        if (t >= 3) { float2 v = *(const float2*)&base[(size_t)(t-3)*(2*DI)];
                      s.x = fmaf(wA.x, v.x, s.x); s.y = fmaf(wB.x, v.y, s.y); }
        if (t >= 2) { float2 v = *(const float2*)&base[(size_t)(t-2)*(2*DI)];
                      s.x = fmaf(wA.y, v.x, s.x); s.y = fmaf(wB.y, v.y, s.y); }
        if (t >= 1) { float2 v = *(const float2*)&base[(size_t)(t-1)*(2*DI)];
                      s.x = fmaf(wA.z, v.x, s.x); s.y = fmaf(wB.z, v.y, s.y); }
        { float2 v = *(const float2*)&base[(size_t)t*(2*DI)];
          s.x = fmaf(wA.w, v.x, s.x); s.y = fmaf(wB.w, v.y, s.y); }
        float2 o;
        o.x = s.x / (1.0f + __expf(-s.x));
        o.y = s.y / (1.0f + __expf(-s.y));
        *(float2*)&g_xc[(size_t)m*DI + d] = o;
    }
}

// ---------------- layernorm (row per block, 256 threads, DM=768) -----------------
__device__ __forceinline__ float block_reduce_sum_256(float v, float* sh, float* bc) {
    #pragma unroll
    for (int o = 16; o > 0; o >>= 1) v += __shfl_xor_sync(0xffffffffu, v, o);
    int w = threadIdx.x >> 5;
    if ((threadIdx.x & 31) == 0) sh[w] = v;
    __syncthreads();
    if (threadIdx.x == 0) {
        float s = 0.0f;
        #pragma unroll
        for (int i = 0; i < 8; i++) s += sh[i];
        *bc = s;
    }
    __syncthreads();
    return *bc;
}

__global__ void ln_kernel(const float* __restrict__ x, const float* __restrict__ w,
                          const float* __restrict__ bias, float* __restrict__ out) {
    __shared__ float sh[8];
    __shared__ float bc;
    int m = blockIdx.x, tid = threadIdx.x;
    const float* xr = x + (size_t)m * DM;
    float v0 = xr[tid], v1 = xr[tid + 256], v2 = xr[tid + 512];
    float mean = block_reduce_sum_256(v0 + v1 + v2, sh, &bc) * (1.0f / DM);
    float d0 = v0 - mean, d1 = v1 - mean, d2 = v2 - mean;
    __syncthreads();
    float var = block_reduce_sum_256(d0*d0 + d1*d1 + d2*d2, sh, &bc) * (1.0f / DM);
    float inv = rsqrtf(var + 1e-12f);
    float* o = out + (size_t)m * DM;
    o[tid]       = d0 * inv * w[tid]       + bias[tid];
    o[tid + 256] = d1 * inv * w[tid + 256] + bias[tid + 256];
    o[tid + 512] = d2 * inv * w[tid + 512] + bias[tid + 512];
}

// ---------------- selective scan: 16 lanes/channel, prefetched loads --------------
__global__ void scan_kernel(const float* __restrict__ A_log_l,
                            const float* __restrict__ Dp_l) {
    int lane = threadIdx.x & 31;
    int warp = threadIdx.x >> 5;
    int widx = blockIdx.x * 8 + warp;
    int ch = widx * 2 + (lane >> 4);       // 2 channels per warp
    int b = ch / DI, d = ch % DI;
    int n = lane & 15;
    float Av = -__expf(A_log_l[d*DSTATE + n]);
    float Dv = Dp_l[d];
    float h = 0.0f;
    int base = b * SEQL;
    float dt = g_dt[(size_t)base*DI + d];
    float xc = g_xc[(size_t)base*DI + d];
    float Bn = g_xdbl[(size_t)base*XDBLN + DTR + n];
    float Cn = g_xdbl[(size_t)base*XDBLN + DTR + DSTATE + n];
    for (int t = 0; t < SEQL; t++) {
        float dtN, xcN, BnN, CnN;
        if (t + 1 < SEQL) {
            int m1 = base + t + 1;
            dtN = g_dt[(size_t)m1*DI + d];
            xcN = g_xc[(size_t)m1*DI + d];
            BnN = g_xdbl[(size_t)m1*XDBLN + DTR + n];
            CnN = g_xdbl[(size_t)m1*XDBLN + DTR + DSTATE + n];
        }
        float dA = __expf(dt * Av);
        h = fmaf(dA, h, (dt * xc) * Bn);
        float p = h * Cn;
        p += __shfl_xor_sync(0xffffffffu, p, 8);
        p += __shfl_xor_sync(0xffffffffu, p, 4);
        p += __shfl_xor_sync(0xffffffffu, p, 2);
        p += __shfl_xor_sync(0xffffffffu, p, 1);
        if (n == 0) {
            int m = base + t;
            float z = g_xz[(size_t)m*(2*DI) + DI + d];
            float y = (p + xc * Dv) * (z / (1.0f + __expf(-z)));
            g_y[(size_t)m*DI + d] = y;
        }
        dt = dtN; xc = xcN; Bn = BnN; Cn = CnN;
    }
}

// ---------------- host launcher ---------------------------------------------------
extern "C" void kernel_launch(void* const* d_in, const int* in_sizes, int n_in,
                              void* d_out, int out_size) {
    const float* pixel     = (const float*)d_in[0];
    const float* noise     = (const float*)d_in[1];
    const float* conv_w    = (const float*)d_in[2];
    const float* conv_b    = (const float*)d_in[3];
    const float* cls_token = (const float*)d_in[4];
    const float* pos_embed = (const float*)d_in[5];
    const float* ln_w      = (const float*)d_in[6];
    const float* ln_b      = (const float*)d_in[7];
    const float* W_in      = (const float*)d_in[8];
    const float* conv1d_w  = (const float*)d_in[9];
    const float* conv1d_b  = (const float*)d_in[10];
    const float* W_x       = (const float*)d_in[11];
    const float* W_dt      = (const float*)d_in[12];
    const float* dt_bias   = (const float*)d_in[13];
    const float* A_log     = (const float*)d_in[14];
    const float* Dp        = (const float*)d_in[15];
    const float* W_out     = (const float*)d_in[16];
    const float* lnf_w     = (const float*)d_in[17];
    const float* lnf_b     = (const float*)d_in[18];

    float* out      = (float*)d_out;
    float* out_h    = out;                       // (8,148,768)
    float* out_mask = out + (size_t)MROWS*DM;    // (8,196)
    float* out_ids  = out_mask + BATCH*NPATCH;   // (8,196) as float

    float *p_patches, *p_h, *p_ln, *p_xz, *p_xc, *p_xdbl, *p_dt, *p_y;
    int *p_rowpatch;
    cudaGetSymbolAddress((void**)&p_patches, g_patches);
    cudaGetSymbolAddress((void**)&p_h,       g_h);
    cudaGetSymbolAddress((void**)&p_ln,      g_ln);
    cudaGetSymbolAddress((void**)&p_xz,      g_xz);
    cudaGetSymbolAddress((void**)&p_xc,      g_xc);
    cudaGetSymbolAddress((void**)&p_xdbl,    g_xdbl);
    cudaGetSymbolAddress((void**)&p_dt,      g_dt);
    cudaGetSymbolAddress((void**)&p_y,       g_y);
    cudaGetSymbolAddress((void**)&p_rowpatch, g_rowpatch);

    const int MB64  = (MROWS + 63) / 64;     // 19
    const int MB128 = (MROWS + 127) / 128;   // 10

    // fused masking + patch gather (launch #1), then patch-embed GEMM (#2)
    maskgather_kernel<<<MROWS, 256>>>(noise, pixel, out_mask, out_ids);
    sgemm3<1><<<dim3(MB64, DM/64, 1), 256>>>(p_patches, conv_w, p_h,
        MROWS, DM, DM, DM, DM, conv_b, cls_token, pos_embed, p_rowpatch);

    for (int l = 0; l < NLAYERS; l++) {
        const float* Wi  = W_in     + (size_t)l * (2*DI) * DM;
        const float* cw  = conv1d_w + (size_t)l * DI * 4;
        const float* cb  = conv1d_b + (size_t)l * DI;
        const float* Wx  = W_x      + (size_t)l * XDBLN * DI;
        const float* Wd  = W_dt     + (size_t)l * DI * DTR;
        const float* db  = dt_bias  + (size_t)l * DI;
        const float* Al  = A_log    + (size_t)l * DI * DSTATE;
        const float* Dl  = Dp       + (size_t)l * DI;
        const float* Wo  = W_out    + (size_t)l * DM * DI;

        // layernorm (#3 in layer 0)
        ln_kernel<<<MROWS, 256>>>(p_h, ln_w + l*DM, ln_b + l*DM, p_ln);

        // (#4, profiled) xz = ln @ W_in^T — bf16x3 tensor GEMM
        mma_bf16x3<0><<<dim3(MB128, (2*DI)/128), 256>>>(
            p_ln, Wi, p_xz, MROWS, 2*DI, DM, DM, DM);

        // depthwise causal conv + silu (also zero-inits xdbl rows)
        conv_silu_kernel<<<MROWS, 256>>>(cw, cb);

        // x_dbl = xc @ W_x^T  (1184 x 80, K=1536) — split-K=4 vector RED
        sgemm_small<64,16,16,2,2><<<dim3(MB64, XDBLN/16, 4), 256>>>(
            p_xc, Wx, p_xdbl, MROWS, XDBLN, DI, DI, DI/4);

        // dt = softplus(x_dbl[:, :48] @ W_dt^T + dt_bias)
        sgemm3<2><<<dim3(MB64, DI/64, 1), 256>>>(p_xdbl, Wd, p_dt,
            MROWS, DI, DTR, XDBLN, DTR, db, nullptr, nullptr, nullptr);

        // selective scan + D skip + gate
        scan_kernel<<<(BATCH*DI)/16, 256>>>(Al, Dl);

        // h += y @ W_out^T — bf16x3 split-K=4 (240 CTAs), vector RED accumulate
        mma_bf16x3<1><<<dim3(MB128, DM/128, 4), 256>>>(
            p_y, Wo, p_h, MROWS, DM, DI, DI, DI/4);
    }

    // final layernorm straight into the output buffer
    ln_kernel<<<MROWS, 256>>>(p_h, lnf_w, lnf_b, out_h);
}

// round 16
// speedup vs baseline: 1.0267x; 1.0083x over previous
#include <cuda_runtime.h>
#include <cuda_bf16.h>
#include <math.h>
#include <stdint.h>

#define BATCH 8
#define NPATCH 196
#define LEN_KEEP 147
#define SEQL 148
#define DM 768
#define DI 1536
#define DSTATE 16
#define DTR 48
#define XDBLN 80
#define NLAYERS 12
#define MROWS (BATCH*SEQL)   // 1184

// ---------------- scratch buffers (device globals; no allocation) ----------------
__device__ float g_patches[MROWS*DM];
__device__ int   g_rowpatch[MROWS];
__device__ float g_h[MROWS*DM];
__device__ float g_ln[MROWS*DM];
__device__ float g_xz[MROWS*2*DI];
__device__ float g_xc[MROWS*DI];
__device__ float g_xdbl[MROWS*XDBLN];
__device__ float g_dt[MROWS*DI];
__device__ float g_y[MROWS*DI];

// ================= low-level helpers =================
__device__ __forceinline__ void gdc_wait() {
    asm volatile("griddepcontrol.wait;" ::: "memory");
}
__device__ __forceinline__ uint32_t smem_u32(const void* p) {
    uint32_t a;
    asm("{ .reg .u64 t; cvta.to.shared.u64 t, %1; cvt.u32.u64 %0, t; }" : "=r"(a) : "l"(p));
    return a;
}
__device__ __forceinline__ void ldsm4(uint32_t* r, uint32_t addr) {
    asm volatile("ldmatrix.sync.aligned.m8n8.x4.shared.b16 {%0,%1,%2,%3}, [%4];"
                 : "=r"(r[0]), "=r"(r[1]), "=r"(r[2]), "=r"(r[3]) : "r"(addr));
}
__device__ __forceinline__ void mma16816(float* d, const uint32_t* a, const uint32_t* b) {
    asm volatile("mma.sync.aligned.m16n8k16.row.col.f32.bf16.bf16.f32 "
                 "{%0,%1,%2,%3}, {%4,%5,%6,%7}, {%8,%9}, {%0,%1,%2,%3};"
                 : "+f"(d[0]), "+f"(d[1]), "+f"(d[2]), "+f"(d[3])
                 : "r"(a[0]), "r"(a[1]), "r"(a[2]), "r"(a[3]), "r"(b[0]), "r"(b[1]));
}
// vector fp32 reduction (sm_90+ base ISA; halves REDG issue count)
__device__ __forceinline__ void red_add_v2(float* ptr, float x, float y) {
    asm volatile("red.global.add.v2.f32 [%0], {%1, %2};"
                 :: "l"(ptr), "f"(x), "f"(y) : "memory");
}

// ======== bf16x3 tensor GEMM: C[M,N] (+)= A[M,lda] * W[N,ldb]^T over K-slice ======
// 128x128 CTA tile, 8 warps (2x4), 64x32 warp tile, 16-float K stages (hi|lo bf16).
// EPI: 0 = plain store, 1 = vector-RED accumulate (for split-K residual add)
template<int EPI>
__global__ __launch_bounds__(256, 2)
void mma_bf16x3(const float* __restrict__ A, const float* __restrict__ W,
                float* __restrict__ C, int M, int N, int lda, int ldb, int Klen) {
    constexpr int PITCH = 40;                 // bf16 elems per row: [hi 16 | lo 16 | pad 8]
    constexpr int ROWB  = PITCH * 2;          // 80 bytes
    constexpr int STAGEB = 128 * ROWB;        // bytes per stage buffer
    __shared__ __align__(16) __nv_bfloat16 As[2][128][PITCH];
    __shared__ __align__(16) __nv_bfloat16 Bs[2][128][PITCH];

    const int tid  = threadIdx.x;
    const int lane = tid & 31;
    const int wid  = tid >> 5;
    const int wm   = wid & 1;                 // 2 warps along M
    const int wn   = wid >> 1;                // 4 warps along N
    const int m0   = blockIdx.x * 128;
    const int n0   = blockIdx.y * 128;
    const int koff = blockIdx.z * Klen;

    float acc[4][4][4];
    #pragma unroll
    for (int i = 0; i < 4; i++)
        #pragma unroll
        for (int j = 0; j < 4; j++)
            #pragma unroll
            for (int q = 0; q < 4; q++) acc[i][j][q] = 0.0f;

    // conflict-free staging mapping
    const int lrow = (tid & 7) | (((tid >> 4) & 1) << 3) | ((tid >> 5) << 4);
    const int lkc  = ((tid >> 3) & 1) * 8;    // k-chunk: floats 0-7 or 8-15
    const int gmA  = m0 + lrow;
    const bool mok = (gmA < M);
    const float* aPtr = A + (size_t)gmA * lda + koff + lkc;
    const float* bPtr = W + (size_t)(n0 + lrow) * ldb + koff + lkc;

    const uint32_t aAddr = smem_u32(&As[0][wm*64 + (lane & 15)][0]) + ((lane >> 4) * 16);
    const uint32_t bAddr = smem_u32(&Bs[0][wn*32 + ((lane >> 4) << 3) + (lane & 7)][0])
                         + (((lane >> 3) & 1) * 16);

    const int KT = Klen / 16;

    // split-store: 8 floats -> hi bf16 16B chunk + lo bf16 16B chunk
    auto split_sts = [&](__nv_bfloat16 (*S)[PITCH], float4 v0, float4 v1) {
        float f[8] = {v0.x, v0.y, v0.z, v0.w, v1.x, v1.y, v1.z, v1.w};
        uint4 hi4, lo4;
        uint32_t* hp = (uint32_t*)&hi4;
        uint32_t* lp = (uint32_t*)&lo4;
        #pragma unroll
        for (int q = 0; q < 4; q++) {
            float x = f[2*q], y = f[2*q+1];
            __nv_bfloat162 h2 = __floats2bfloat162_rn(x, y);
            float2 hf = __bfloat1622float2(h2);
            __nv_bfloat162 l2 = __floats2bfloat162_rn(x - hf.x, y - hf.y);
            hp[q] = *(uint32_t*)&h2;
            lp[q] = *(uint32_t*)&l2;
        }
        *(uint4*)&S[lrow][lkc]      = hi4;
        *(uint4*)&S[lrow][16 + lkc] = lo4;
    };

    // wait for producer grid before first dependent read (A and, for EPI=1, C)
    gdc_wait();

    // ---- stage 0 ----
    {
        float4 va0 = make_float4(0,0,0,0), va1 = va0;
        if (mok) { va0 = *(const float4*)aPtr; va1 = *(const float4*)(aPtr + 4); }
        float4 vb0 = *(const float4*)bPtr, vb1 = *(const float4*)(bPtr + 4);
        split_sts(As[0], va0, va1);
        split_sts(Bs[0], vb0, vb1);
    }
    __syncthreads();

    int s = 0;
    for (int kt = 0; kt < KT; kt++) {
        float4 va0, va1, vb0, vb1;
        if (kt + 1 < KT) {
            int k0 = (kt + 1) * 16;
            va0 = make_float4(0,0,0,0); va1 = va0;
            if (mok) { va0 = *(const float4*)(aPtr + k0); va1 = *(const float4*)(aPtr + k0 + 4); }
            vb0 = *(const float4*)(bPtr + k0); vb1 = *(const float4*)(bPtr + k0 + 4);
        }

        // ---- compute stage s: acc += Ah*Bh + Ah*Bl + Al*Bh ----
        {
            const uint32_t aS = aAddr + s * STAGEB;
            const uint32_t bS = bAddr + s * STAGEB;
            uint32_t Af[4][4], Bh[4][2], Bl[4][2], t[4];

            #pragma unroll
            for (int mf = 0; mf < 4; mf++) ldsm4(Af[mf], aS + mf * 16 * ROWB);     // A hi
            ldsm4(t, bS);                 Bh[0][0]=t[0]; Bh[0][1]=t[1]; Bh[1][0]=t[2]; Bh[1][1]=t[3];
            ldsm4(t, bS + 16 * ROWB);     Bh[2][0]=t[0]; Bh[2][1]=t[1]; Bh[3][0]=t[2]; Bh[3][1]=t[3];
            #pragma unroll
            for (int mf = 0; mf < 4; mf++)
                #pragma unroll
                for (int nf = 0; nf < 4; nf++) mma16816(acc[mf][nf], Af[mf], Bh[nf]);

            ldsm4(t, bS + 32);            Bl[0][0]=t[0]; Bl[0][1]=t[1]; Bl[1][0]=t[2]; Bl[1][1]=t[3];
            ldsm4(t, bS + 16*ROWB + 32);  Bl[2][0]=t[0]; Bl[2][1]=t[1]; Bl[3][0]=t[2]; Bl[3][1]=t[3];
            #pragma unroll
            for (int mf = 0; mf < 4; mf++)
                #pragma unroll
                for (int nf = 0; nf < 4; nf++) mma16816(acc[mf][nf], Af[mf], Bl[nf]);

            #pragma unroll
            for (int mf = 0; mf < 4; mf++) ldsm4(Af[mf], aS + mf * 16 * ROWB + 32); // A lo
            #pragma unroll
            for (int mf = 0; mf < 4; mf++)
                #pragma unroll
                for (int nf = 0; nf < 4; nf++) mma16816(acc[mf][nf], Af[mf], Bh[nf]);
        }

        if (kt + 1 < KT) {
            int sn = s ^ 1;
            split_sts(As[sn], va0, va1);
            split_sts(Bs[sn], vb0, vb1);
            __syncthreads();
            s = sn;
        }
    }

    // ---- epilogue ----
    #pragma unroll
    for (int mf = 0; mf < 4; mf++) {
        int r0 = m0 + wm*64 + mf*16 + (lane >> 2);
        #pragma unroll
        for (int nf = 0; nf < 4; nf++) {
            int c = n0 + wn*32 + nf*8 + (lane & 3)*2;
            if (EPI == 0) {
                if (r0 < M)     *(float2*)&C[(size_t)r0 * N + c]     = make_float2(acc[mf][nf][0], acc[mf][nf][1]);
                if (r0 + 8 < M) *(float2*)&C[(size_t)(r0+8) * N + c] = make_float2(acc[mf][nf][2], acc[mf][nf][3]);
            } else {
                if (r0 < M)
                    red_add_v2(&C[(size_t)r0 * N + c],     acc[mf][nf][0], acc[mf][nf][1]);
                if (r0 + 8 < M)
                    red_add_v2(&C[(size_t)(r0+8) * N + c], acc[mf][nf][2], acc[mf][nf][3]);
            }
        }
    }
}

// ---------------- packed f32x2 helpers (FFMA2 kernels) ----------------------------
__device__ __forceinline__ void ffma2(unsigned long long& acc,
                                      unsigned long long a, unsigned long long b) {
    asm("fma.rn.f32x2 %0, %1, %2, %0;" : "+l"(acc) : "l"(a), "l"(b));
}
__device__ __forceinline__ unsigned long long pack2(float x, float y) {
    unsigned long long r;
    asm("mov.b64 %0, {%1, %2};" : "=l"(r) : "f"(x), "f"(y));
    return r;
}
__device__ __forceinline__ float2 unpack2(unsigned long long v) {
    float2 f;
    asm("mov.b64 {%0, %1}, %2;" : "=f"(f.x), "=f"(f.y) : "l"(v));
    return f;
}

// -------- fused masking + gather: every block recomputes ranks from noise --------
__global__ void maskgather_kernel(const float* __restrict__ noise,
                                  const float* __restrict__ pix,
                                  float* __restrict__ out_mask,
                                  float* __restrict__ out_ids) {
    __shared__ float s[NPATCH];
    __shared__ int p_sel;
    int m = blockIdx.x;
    int t = m % SEQL, b = m / SEQL;
    int tid = threadIdx.x;
    gdc_wait();                      // predecessor = previous replay's final ln
    if (tid < NPATCH) s[tid] = noise[b*NPATCH + tid];
    __syncthreads();
    int rank = -1;
    if (tid < NPATCH) {
        float v = s[tid];
        rank = 0;
        #pragma unroll 4
        for (int j = 0; j < NPATCH; j++) {
            float u = s[j];
            rank += (u < v) || (u == v && j < tid);
        }
    }
    if (t == 0) {
        if (tid < NPATCH) {
            out_mask[b*NPATCH + tid] = (rank >= LEN_KEEP) ? 1.0f : 0.0f;
            out_ids [b*NPATCH + tid] = (float)rank;
        }
        if (tid == 0) g_rowpatch[m] = -1;
        for (int k = tid; k < DM; k += blockDim.x) g_patches[m*DM + k] = 0.0f;
        return;
    }
    if (rank == t - 1) p_sel = tid;      // exactly one thread matches
    __syncthreads();
    int p = p_sel;
    if (tid == 0) g_rowpatch[m] = p;
    int pi = p / 14, pj = p % 14;
    for (int k = tid; k < DM; k += blockDim.x) {
        int c = k >> 8, rem = k & 255, r = rem >> 4, cc = rem & 15;
        g_patches[m*DM + k] =
            pix[((size_t)(b*3 + c)*224 + pi*16 + r)*224 + pj*16 + cc];
    }
}

// =============== FFMA2 SGEMM (patch-embed and dt) =================================
// EPI: 1 patch-embed | 2 softplus(+dt_bias)
template<int EPI>
__global__ __launch_bounds__(256)
void sgemm3(const float* __restrict__ A, const float* __restrict__ W,
            float* __restrict__ C, int M, int N, int K, int lda, int Klen,
            const float* __restrict__ ep0, const float* __restrict__ ep1,
            const float* __restrict__ ep2, const int* __restrict__ rowinfo) {
    constexpr int BM = 64, BN = 64, BK = 16;
    constexpr int PA = 132;
    constexpr int PB = 68;
    __shared__ __align__(16) float As2[2][BK][PA];
    __shared__ __align__(16) float Bs [2][BK][PB];
    const int tid = threadIdx.x;
    const int m0 = blockIdx.x * BM;
    const int n0 = blockIdx.y * BN;
    const int koff = blockIdx.z * Klen;
    const int tx = tid & 15;
    const int ty = tid >> 4;
    unsigned long long acc[4][2];
    #pragma unroll
    for (int i = 0; i < 4; i++) { acc[i][0] = 0ull; acc[i][1] = 0ull; }
    const int KT = Klen / BK;
    const int li = tid >> 4, lj = tid & 15;
    gdc_wait();
    #pragma unroll
    for (int r = 0; r < 4; r++) {
        int i = li + r*16;
        int gm = m0 + i;
        float va = (gm < M) ? A[(size_t)gm * lda + koff + lj] : 0.0f;
        *(unsigned long long*)&As2[0][lj][2*i] = pack2(va, va);
        Bs[0][lj][i] = W[(size_t)(n0 + i) * K + koff + lj];
    }
    __syncthreads();
    int s = 0;
    for (int kt = 0; kt < KT; kt++) {
        float ra[4], rb[4];
        if (kt + 1 < KT) {
            int k0 = koff + (kt + 1) * BK;
            #pragma unroll
            for (int r = 0; r < 4; r++) {
                int i = li + r*16;
                int gm = m0 + i;
                ra[r] = (gm < M) ? A[(size_t)gm * lda + k0 + lj] : 0.0f;
                rb[r] = W[(size_t)(n0 + i) * K + k0 + lj];
            }
        }
        #pragma unroll
        for (int kk = 0; kk < BK; kk++) {
            ulonglong2 a01 = *(const ulonglong2*)&As2[s][kk][ty*8];
            ulonglong2 a23 = *(const ulonglong2*)&As2[s][kk][ty*8 + 4];
            ulonglong2 bq  = *(const ulonglong2*)&Bs [s][kk][tx*4];
            ffma2(acc[0][0], a01.x, bq.x); ffma2(acc[0][1], a01.x, bq.y);
            ffma2(acc[1][0], a01.y, bq.x); ffma2(acc[1][1], a01.y, bq.y);
            ffma2(acc[2][0], a23.x, bq.x); ffma2(acc[2][1], a23.x, bq.y);
            ffma2(acc[3][0], a23.y, bq.x); ffma2(acc[3][1], a23.y, bq.y);
        }
        if (kt + 1 < KT) {
            int sn = s ^ 1;
            #pragma unroll
            for (int r = 0; r < 4; r++) {
                int i = li + r*16;
                *(unsigned long long*)&As2[sn][lj][2*i] = pack2(ra[r], ra[r]);
                Bs[sn][lj][i] = rb[r];
            }
            __syncthreads();
            s = sn;
        }
    }
    #pragma unroll
    for (int i = 0; i < 4; i++) {
        int m = m0 + ty*4 + i;
        if (m >= M) continue;
        int rp = 0;
        if (EPI == 1) rp = rowinfo[m];
        #pragma unroll
        for (int j = 0; j < 2; j++) {
            float2 v2 = unpack2(acc[i][j]);
            int n = n0 + tx*4 + j*2;
            if (EPI == 2) {
                float x0 = v2.x + ep0[n],   x1 = v2.y + ep0[n+1];
                v2.x = (x0 > 20.0f) ? x0 : log1pf(__expf(x0));
                v2.y = (x1 > 20.0f) ? x1 : log1pf(__expf(x1));
                *(float2*)&C[(size_t)m * N + n] = v2;
            } else { // EPI == 1
                float vv[2] = {v2.x, v2.y};
                #pragma unroll
                for (int q = 0; q < 2; q++) {
                    int nn = n + q;
                    float v = vv[q];
                    if (rp < 0) v = ep1[nn] + ep2[nn];
                    else        v = v + ep0[nn] + ep2[(size_t)(1+rp)*DM + nn];
                    C[(size_t)m * N + nn] = v;
                }
            }
        }
    }
}

// ---------------- small SGEMM for x_dbl (N=80), split-K with vector RED -----------
// Thread tile (2,2): 4 LDS per 4 FMA; epilogue = red.add.v2 per thread-row.
template<int BM, int BN, int BK, int TM, int TN>
__global__ __launch_bounds__(256)
void sgemm_small(const float* __restrict__ A, const float* __restrict__ W,
                 float* __restrict__ C, int M, int N, int K, int lda, int Klen) {
    __shared__ float As[BK][BM + 4];
    __shared__ float Bs[BK][BN + 4];
    const int tid = threadIdx.x;
    const int m0 = blockIdx.x * BM;
    const int n0 = blockIdx.y * BN;
    const int koff = blockIdx.z * Klen;
    constexpr int CT = BN / TN;
    const int tx = tid % CT;
    const int ty = tid / CT;
    float acc[TM][TN];
    #pragma unroll
    for (int i = 0; i < TM; i++)
        #pragma unroll
        for (int j = 0; j < TN; j++) acc[i][j] = 0.0f;
    constexpr int AREP = (BM * BK) / 256;
    constexpr int BREP = (BN * BK + 255) / 256;
    gdc_wait();
    for (int k0 = koff; k0 < koff + Klen; k0 += BK) {
        #pragma unroll
        for (int r = 0; r < AREP; r++) {
            int idx = tid + r * 256;
            int i = idx / BK, j = idx % BK;
            int gm = m0 + i;
            As[j][i] = (gm < M) ? A[(size_t)gm * lda + k0 + j] : 0.0f;
        }
        #pragma unroll
        for (int r = 0; r < BREP; r++) {
            int idx = tid + r * 256;
            if (idx < BN * BK) {
                int i = idx / BK, j = idx % BK;
                Bs[j][i] = W[(size_t)(n0 + i) * K + k0 + j];
            }
        }
        __syncthreads();
        #pragma unroll
        for (int kk = 0; kk < BK; kk++) {
            float a[TM], bb[TN];
            #pragma unroll
            for (int i = 0; i < TM; i++) a[i] = As[kk][ty*TM + i];
            #pragma unroll
            for (int j = 0; j < TN; j++) bb[j] = Bs[kk][tx*TN + j];
            #pragma unroll
            for (int i = 0; i < TM; i++)
                #pragma unroll
                for (int j = 0; j < TN; j++)
                    acc[i][j] = fmaf(a[i], bb[j], acc[i][j]);
        }
        __syncthreads();
    }
    #pragma unroll
    for (int i = 0; i < TM; i++) {
        int m = m0 + ty*TM + i;
        if (m >= M) continue;
        // TN == 2 and tx*TN is even -> 8B-aligned pair
        red_add_v2(&C[(size_t)m * N + n0 + tx*TN], acc[i][0], acc[i][1]);
    }
}

// ------- depthwise causal conv1d (k=4) + SiLU, float2 vectorized; zeroes xdbl ----
__global__ void conv_silu_kernel(const float* __restrict__ cw,
                                 const float* __restrict__ cb) {
    int m = blockIdx.x;
    int t = m % SEQL, b = m / SEQL;
    gdc_wait();
    if (threadIdx.x < XDBLN) g_xdbl[(size_t)m*XDBLN + threadIdx.x] = 0.0f;
    for (int d2 = threadIdx.x; d2 < DI/2; d2 += blockDim.x) {
        int d = d2 * 2;
        float4 wA = *(const float4*)&cw[d*4];
        float4 wB = *(const float4*)&cw[d*4 + 4];
        float2 s = *(const float2*)&cb[d];
        const float* base = g_xz + (size_t)(b*SEQL) * (2*DI) + d;
        if (t >= 3) { float2 v = *(const float2*)&base[(size_t)(t-3)*(2*DI)];
                      s.x = fmaf(wA.x, v.x, s.x); s.y = fmaf(wB.x, v.y, s.y); }
        if (t >= 2) { float2 v = *(const float2*)&base[(size_t)(t-2)*(2*DI)];
                      s.x = fmaf(wA.y, v.x, s.x); s.y = fmaf(wB.y, v.y, s.y); }
        if (t >= 1) { float2 v = *(const float2*)&base[(size_t)(t-1)*(2*DI)];
                      s.x = fmaf(wA.z, v.x, s.x); s.y = fmaf(wB.z, v.y, s.y); }
        { float2 v = *(const float2*)&base[(size_t)t*(2*DI)];
          s.x = fmaf(wA.w, v.x, s.x); s.y = fmaf(wB.w, v.y, s.y); }
        float2 o;
        o.x = s.x / (1.0f + __expf(-s.x));
        o.y = s.y / (1.0f + __expf(-s.y));
        *(float2*)&g_xc[(size_t)m*DI + d] = o;
    }
}

// ---------------- layernorm (row per block, 256 threads, DM=768) -----------------
__device__ __forceinline__ float block_reduce_sum_256(float v, float* sh, float* bc) {
    #pragma unroll
    for (int o = 16; o > 0; o >>= 1) v += __shfl_xor_sync(0xffffffffu, v, o);
    int w = threadIdx.x >> 5;
    if ((threadIdx.x & 31) == 0) sh[w] = v;
    __syncthreads();
    if (threadIdx.x == 0) {
        float s = 0.0f;
        #pragma unroll
        for (int i = 0; i < 8; i++) s += sh[i];
        *bc = s;
    }
    __syncthreads();
    return *bc;
}

__global__ void ln_kernel(const float* __restrict__ x, const float* __restrict__ w,
                          const float* __restrict__ bias, float* __restrict__ out) {
    __shared__ float sh[8];
    __shared__ float bc;
    int m = blockIdx.x, tid = threadIdx.x;
    gdc_wait();
    const float* xr = x + (size_t)m * DM;
    float v0 = xr[tid], v1 = xr[tid + 256], v2 = xr[tid + 512];
    float mean = block_reduce_sum_256(v0 + v1 + v2, sh, &bc) * (1.0f / DM);
    float d0 = v0 - mean, d1 = v1 - mean, d2 = v2 - mean;
    __syncthreads();
    float var = block_reduce_sum_256(d0*d0 + d1*d1 + d2*d2, sh, &bc) * (1.0f / DM);
    float inv = rsqrtf(var + 1e-12f);
    float* o = out + (size_t)m * DM;
    o[tid]       = d0 * inv * w[tid]       + bias[tid];
    o[tid + 256] = d1 * inv * w[tid + 256] + bias[tid + 256];
    o[tid + 512] = d2 * inv * w[tid + 512] + bias[tid + 512];
}

// ---------------- selective scan: 16 lanes/channel, prefetched loads --------------
__global__ void scan_kernel(const float* __restrict__ A_log_l,
                            const float* __restrict__ Dp_l) {
    int lane = threadIdx.x & 31;
    int warp = threadIdx.x >> 5;
    int widx = blockIdx.x * 8 + warp;
    int ch = widx * 2 + (lane >> 4);       // 2 channels per warp
    int b = ch / DI, d = ch % DI;
    int n = lane & 15;
    // independent preamble (reads immutable inputs only)
    float Av = -__expf(A_log_l[d*DSTATE + n]);
    float Dv = Dp_l[d];
    float h = 0.0f;
    int base = b * SEQL;
    gdc_wait();                            // now wait for dt/xc/xdbl producers
    float dt = g_dt[(size_t)base*DI + d];
    float xc = g_xc[(size_t)base*DI + d];
    float Bn = g_xdbl[(size_t)base*XDBLN + DTR + n];
    float Cn = g_xdbl[(size_t)base*XDBLN + DTR + DSTATE + n];
    for (int t = 0; t < SEQL; t++) {
        float dtN, xcN, BnN, CnN;
        if (t + 1 < SEQL) {
            int m1 = base + t + 1;
            dtN = g_dt[(size_t)m1*DI + d];
            xcN = g_xc[(size_t)m1*DI + d];
            BnN = g_xdbl[(size_t)m1*XDBLN + DTR + n];
            CnN = g_xdbl[(size_t)m1*XDBLN + DTR + DSTATE + n];
        }
        float dA = __expf(dt * Av);
        h = fmaf(dA, h, (dt * xc) * Bn);
        float p = h * Cn;
        p += __shfl_xor_sync(0xffffffffu, p, 8);
        p += __shfl_xor_sync(0xffffffffu, p, 4);
        p += __shfl_xor_sync(0xffffffffu, p, 2);
        p += __shfl_xor_sync(0xffffffffu, p, 1);
        if (n == 0) {
            int m = base + t;
            float z = g_xz[(size_t)m*(2*DI) + DI + d];
            float y = (p + xc * Dv) * (z / (1.0f + __expf(-z)));
            g_y[(size_t)m*DI + d] = y;
        }
        dt = dtN; xc = xcN; Bn = BnN; Cn = CnN;
    }
}

// ---------------- PDL launch helper ------------------------------------------------
template<typename K, typename... Args>
static inline void launchP(K kern, dim3 g, dim3 b, Args... args) {
    cudaLaunchConfig_t cfg = {};
    cfg.gridDim = g;
    cfg.blockDim = b;
    cfg.dynamicSmemBytes = 0;
    cudaLaunchAttribute attrs[1];
    attrs[0].id = cudaLaunchAttributeProgrammaticStreamSerialization;
    attrs[0].val.programmaticStreamSerializationAllowed = 1;
    cfg.attrs = attrs;
    cfg.numAttrs = 1;
    cudaLaunchKernelEx(&cfg, kern, args...);
}

// ---------------- host launcher ---------------------------------------------------
extern "C" void kernel_launch(void* const* d_in, const int* in_sizes, int n_in,
                              void* d_out, int out_size) {
    const float* pixel     = (const float*)d_in[0];
    const float* noise     = (const float*)d_in[1];
    const float* conv_w    = (const float*)d_in[2];
    const float* conv_b    = (const float*)d_in[3];
    const float* cls_token = (const float*)d_in[4];
    const float* pos_embed = (const float*)d_in[5];
    const float* ln_w      = (const float*)d_in[6];
    const float* ln_b      = (const float*)d_in[7];
    const float* W_in      = (const float*)d_in[8];
    const float* conv1d_w  = (const float*)d_in[9];
    const float* conv1d_b  = (const float*)d_in[10];
    const float* W_x       = (const float*)d_in[11];
    const float* W_dt      = (const float*)d_in[12];
    const float* dt_bias   = (const float*)d_in[13];
    const float* A_log     = (const float*)d_in[14];
    const float* Dp        = (const float*)d_in[15];
    const float* W_out     = (const float*)d_in[16];
    const float* lnf_w     = (const float*)d_in[17];
    const float* lnf_b     = (const float*)d_in[18];

    float* out      = (float*)d_out;
    float* out_h    = out;                       // (8,148,768)
    float* out_mask = out + (size_t)MROWS*DM;    // (8,196)
    float* out_ids  = out_mask + BATCH*NPATCH;   // (8,196) as float

    float *p_patches, *p_h, *p_ln, *p_xz, *p_xc, *p_xdbl, *p_dt, *p_y;
    int *p_rowpatch;
    cudaGetSymbolAddress((void**)&p_patches, g_patches);
    cudaGetSymbolAddress((void**)&p_h,       g_h);
    cudaGetSymbolAddress((void**)&p_ln,      g_ln);
    cudaGetSymbolAddress((void**)&p_xz,      g_xz);
    cudaGetSymbolAddress((void**)&p_xc,      g_xc);
    cudaGetSymbolAddress((void**)&p_xdbl,    g_xdbl);
    cudaGetSymbolAddress((void**)&p_dt,      g_dt);
    cudaGetSymbolAddress((void**)&p_y,       g_y);
    cudaGetSymbolAddress((void**)&p_rowpatch, g_rowpatch);

    const int MB64  = (MROWS + 63) / 64;     // 19
    const int MB128 = (MROWS + 127) / 128;   // 10

    // fused masking + patch gather, then patch-embed GEMM (both PDL-chained)
    launchP(maskgather_kernel, dim3(MROWS), dim3(256),
            noise, pixel, out_mask, out_ids);
    launchP(sgemm3<1>, dim3(MB64, DM/64, 1), dim3(256),
            (const float*)p_patches, conv_w, p_h,
            MROWS, DM, DM, DM, DM, conv_b, cls_token, pos_embed,
            (const int*)p_rowpatch);

    for (int l = 0; l < NLAYERS; l++) {
        const float* Wi  = W_in     + (size_t)l * (2*DI) * DM;
        const float* cw  = conv1d_w + (size_t)l * DI * 4;
        const float* cb  = conv1d_b + (size_t)l * DI;
        const float* Wx  = W_x      + (size_t)l * XDBLN * DI;
        const float* Wd  = W_dt     + (size_t)l * DI * DTR;
        const float* db  = dt_bias  + (size_t)l * DI;
        const float* Al  = A_log    + (size_t)l * DI * DSTATE;
        const float* Dl  = Dp       + (size_t)l * DI;
        const float* Wo  = W_out    + (size_t)l * DM * DI;

        // layernorm
        launchP(ln_kernel, dim3(MROWS), dim3(256),
                (const float*)p_h, ln_w + l*DM, ln_b + l*DM, p_ln);

        // xz = ln @ W_in^T — bf16x3 tensor GEMM
        launchP(mma_bf16x3<0>, dim3(MB128, (2*DI)/128, 1), dim3(256),
                (const float*)p_ln, Wi, p_xz, MROWS, 2*DI, DM, DM, DM);

        // depthwise causal conv + silu (also zero-inits xdbl rows)
        launchP(conv_silu_kernel, dim3(MROWS), dim3(256), cw, cb);

        // x_dbl = xc @ W_x^T — split-K=4 vector RED
        launchP(sgemm_small<64,16,16,2,2>, dim3(MB64, XDBLN/16, 4), dim3(256),
                (const float*)p_xc, Wx, p_xdbl, MROWS, XDBLN, DI, DI, DI/4);

        // dt = softplus(x_dbl[:, :48] @ W_dt^T + dt_bias)
        launchP(sgemm3<2>, dim3(MB64, DI/64, 1), dim3(256),
                (const float*)p_xdbl, Wd, p_dt,
                MROWS, DI, DTR, XDBLN, DTR, db,
                (const float*)nullptr, (const float*)nullptr,
                (const int*)nullptr);

        // selective scan + D skip + gate
        launchP(scan_kernel, dim3((BATCH*DI)/16), dim3(256), Al, Dl);

        // h += y @ W_out^T — bf16x3 split-K=4, vector RED accumulate
        launchP(mma_bf16x3<1>, dim3(MB128, DM/128, 4), dim3(256),
                (const float*)p_y, Wo, p_h, MROWS, DM, DI, DI, DI/4);
    }

    // final layernorm straight into the output buffer
    launchP(ln_kernel, dim3(MROWS), dim3(256),
            (const float*)p_h, lnf_w, lnf_b, out_h);
}

// round 17
// speedup vs baseline: 1.0805x; 1.0525x over previous
#include <cuda_runtime.h>
#include <cuda_bf16.h>
#include <math.h>
#include <stdint.h>

#define BATCH 8
#define NPATCH 196
#define LEN_KEEP 147
#define SEQL 148
#define DM 768
#define DI 1536
#define DSTATE 16
#define DTR 48
#define XDBLN 80
#define NLAYERS 12
#define MROWS (BATCH*SEQL)   // 1184

// ---------------- scratch buffers (device globals; no allocation) ----------------
__device__ float g_patches[MROWS*DM];
__device__ int   g_rowpatch[MROWS];
__device__ float g_h[MROWS*DM];
__device__ float g_ln[MROWS*DM];
__device__ float g_xz[MROWS*2*DI];
__device__ float g_xc[MROWS*DI];
__device__ float g_xdbl[MROWS*XDBLN];
__device__ float g_dt[MROWS*DI];
__device__ float g_y[MROWS*DI];

// ================= low-level helpers =================
__device__ __forceinline__ void gdc_wait() {
    asm volatile("griddepcontrol.wait;" ::: "memory");
}
__device__ __forceinline__ uint32_t smem_u32(const void* p) {
    uint32_t a;
    asm("{ .reg .u64 t; cvta.to.shared.u64 t, %1; cvt.u32.u64 %0, t; }" : "=r"(a) : "l"(p));
    return a;
}
__device__ __forceinline__ void ldsm4(uint32_t* r, uint32_t addr) {
    asm volatile("ldmatrix.sync.aligned.m8n8.x4.shared.b16 {%0,%1,%2,%3}, [%4];"
                 : "=r"(r[0]), "=r"(r[1]), "=r"(r[2]), "=r"(r[3]) : "r"(addr));
}
__device__ __forceinline__ void mma16816(float* d, const uint32_t* a, const uint32_t* b) {
    asm volatile("mma.sync.aligned.m16n8k16.row.col.f32.bf16.bf16.f32 "
                 "{%0,%1,%2,%3}, {%4,%5,%6,%7}, {%8,%9}, {%0,%1,%2,%3};"
                 : "+f"(d[0]), "+f"(d[1]), "+f"(d[2]), "+f"(d[3])
                 : "r"(a[0]), "r"(a[1]), "r"(a[2]), "r"(a[3]), "r"(b[0]), "r"(b[1]));
}
// vector / scalar fp32 reductions (sm_90+ base ISA)
__device__ __forceinline__ void red_add_v2(float* ptr, float x, float y) {
    asm volatile("red.global.add.v2.f32 [%0], {%1, %2};"
                 :: "l"(ptr), "f"(x), "f"(y) : "memory");
}
__device__ __forceinline__ void red_add1(float* ptr, float v) {
    asm volatile("red.global.add.f32 [%0], %1;" :: "l"(ptr), "f"(v) : "memory");
}

// ======== bf16x3 tensor GEMM: C[M,N] (+)= A[M,lda] * W[N,ldb]^T over K-slice ======
// 128x128 CTA tile, 8 warps (2x4), 64x32 warp tile, 16-float K stages (hi|lo bf16).
// EPI: 0 = plain store, 1 = vector-RED accumulate (for split-K residual add)
template<int EPI>
__global__ __launch_bounds__(256, 2)
void mma_bf16x3(const float* __restrict__ A, const float* __restrict__ W,
                float* __restrict__ C, int M, int N, int lda, int ldb, int Klen) {
    constexpr int PITCH = 40;                 // bf16 elems per row: [hi 16 | lo 16 | pad 8]
    constexpr int ROWB  = PITCH * 2;          // 80 bytes
    constexpr int STAGEB = 128 * ROWB;        // bytes per stage buffer
    __shared__ __align__(16) __nv_bfloat16 As[2][128][PITCH];
    __shared__ __align__(16) __nv_bfloat16 Bs[2][128][PITCH];

    const int tid  = threadIdx.x;
    const int lane = tid & 31;
    const int wid  = tid >> 5;
    const int wm   = wid & 1;                 // 2 warps along M
    const int wn   = wid >> 1;                // 4 warps along N
    const int m0   = blockIdx.x * 128;
    const int n0   = blockIdx.y * 128;
    const int koff = blockIdx.z * Klen;

    float acc[4][4][4];
    #pragma unroll
    for (int i = 0; i < 4; i++)
        #pragma unroll
        for (int j = 0; j < 4; j++)
            #pragma unroll
            for (int q = 0; q < 4; q++) acc[i][j][q] = 0.0f;

    // conflict-free staging mapping
    const int lrow = (tid & 7) | (((tid >> 4) & 1) << 3) | ((tid >> 5) << 4);
    const int lkc  = ((tid >> 3) & 1) * 8;    // k-chunk: floats 0-7 or 8-15
    const int gmA  = m0 + lrow;
    const bool mok = (gmA < M);
    const float* aPtr = A + (size_t)gmA * lda + koff + lkc;
    const float* bPtr = W + (size_t)(n0 + lrow) * ldb + koff + lkc;

    const uint32_t aAddr = smem_u32(&As[0][wm*64 + (lane & 15)][0]) + ((lane >> 4) * 16);
    const uint32_t bAddr = smem_u32(&Bs[0][wn*32 + ((lane >> 4) << 3) + (lane & 7)][0])
                         + (((lane >> 3) & 1) * 16);

    const int KT = Klen / 16;

    // split-store: 8 floats -> hi bf16 16B chunk + lo bf16 16B chunk
    auto split_sts = [&](__nv_bfloat16 (*S)[PITCH], float4 v0, float4 v1) {
        float f[8] = {v0.x, v0.y, v0.z, v0.w, v1.x, v1.y, v1.z, v1.w};
        uint4 hi4, lo4;
        uint32_t* hp = (uint32_t*)&hi4;
        uint32_t* lp = (uint32_t*)&lo4;
        #pragma unroll
        for (int q = 0; q < 4; q++) {
            float x = f[2*q], y = f[2*q+1];
            __nv_bfloat162 h2 = __floats2bfloat162_rn(x, y);
            float2 hf = __bfloat1622float2(h2);
            __nv_bfloat162 l2 = __floats2bfloat162_rn(x - hf.x, y - hf.y);
            hp[q] = *(uint32_t*)&h2;
            lp[q] = *(uint32_t*)&l2;
        }
        *(uint4*)&S[lrow][lkc]      = hi4;
        *(uint4*)&S[lrow][16 + lkc] = lo4;
    };

    // wait for producer grid before first dependent read (A and, for EPI=1, C)
    gdc_wait();

    // ---- stage 0 ----
    {
        float4 va0 = make_float4(0,0,0,0), va1 = va0;
        if (mok) { va0 = *(const float4*)aPtr; va1 = *(const float4*)(aPtr + 4); }
        float4 vb0 = *(const float4*)bPtr, vb1 = *(const float4*)(bPtr + 4);
        split_sts(As[0], va0, va1);
        split_sts(Bs[0], vb0, vb1);
    }
    __syncthreads();

    int s = 0;
    for (int kt = 0; kt < KT; kt++) {
        float4 va0, va1, vb0, vb1;
        if (kt + 1 < KT) {
            int k0 = (kt + 1) * 16;
            va0 = make_float4(0,0,0,0); va1 = va0;
            if (mok) { va0 = *(const float4*)(aPtr + k0); va1 = *(const float4*)(aPtr + k0 + 4); }
            vb0 = *(const float4*)(bPtr + k0); vb1 = *(const float4*)(bPtr + k0 + 4);
        }

        // ---- compute stage s: acc += Ah*Bh + Ah*Bl + Al*Bh ----
        {
            const uint32_t aS = aAddr + s * STAGEB;
            const uint32_t bS = bAddr + s * STAGEB;
            uint32_t Af[4][4], Bh[4][2], Bl[4][2], t[4];

            #pragma unroll
            for (int mf = 0; mf < 4; mf++) ldsm4(Af[mf], aS + mf * 16 * ROWB);     // A hi
            ldsm4(t, bS);                 Bh[0][0]=t[0]; Bh[0][1]=t[1]; Bh[1][0]=t[2]; Bh[1][1]=t[3];
            ldsm4(t, bS + 16 * ROWB);     Bh[2][0]=t[0]; Bh[2][1]=t[1]; Bh[3][0]=t[2]; Bh[3][1]=t[3];
            #pragma unroll
            for (int mf = 0; mf < 4; mf++)
                #pragma unroll
                for (int nf = 0; nf < 4; nf++) mma16816(acc[mf][nf], Af[mf], Bh[nf]);

            ldsm4(t, bS + 32);            Bl[0][0]=t[0]; Bl[0][1]=t[1]; Bl[1][0]=t[2]; Bl[1][1]=t[3];
            ldsm4(t, bS + 16*ROWB + 32);  Bl[2][0]=t[0]; Bl[2][1]=t[1]; Bl[3][0]=t[2]; Bl[3][1]=t[3];
            #pragma unroll
            for (int mf = 0; mf < 4; mf++)
                #pragma unroll
                for (int nf = 0; nf < 4; nf++) mma16816(acc[mf][nf], Af[mf], Bl[nf]);

            #pragma unroll
            for (int mf = 0; mf < 4; mf++) ldsm4(Af[mf], aS + mf * 16 * ROWB + 32); // A lo
            #pragma unroll
            for (int mf = 0; mf < 4; mf++)
                #pragma unroll
                for (int nf = 0; nf < 4; nf++) mma16816(acc[mf][nf], Af[mf], Bh[nf]);
        }

        if (kt + 1 < KT) {
            int sn = s ^ 1;
            split_sts(As[sn], va0, va1);
            split_sts(Bs[sn], vb0, vb1);
            __syncthreads();
            s = sn;
        }
    }

    // ---- epilogue ----
    #pragma unroll
    for (int mf = 0; mf < 4; mf++) {
        int r0 = m0 + wm*64 + mf*16 + (lane >> 2);
        #pragma unroll
        for (int nf = 0; nf < 4; nf++) {
            int c = n0 + wn*32 + nf*8 + (lane & 3)*2;
            if (EPI == 0) {
                if (r0 < M)     *(float2*)&C[(size_t)r0 * N + c]     = make_float2(acc[mf][nf][0], acc[mf][nf][1]);
                if (r0 + 8 < M) *(float2*)&C[(size_t)(r0+8) * N + c] = make_float2(acc[mf][nf][2], acc[mf][nf][3]);
            } else {
                if (r0 < M)
                    red_add_v2(&C[(size_t)r0 * N + c],     acc[mf][nf][0], acc[mf][nf][1]);
                if (r0 + 8 < M)
                    red_add_v2(&C[(size_t)(r0+8) * N + c], acc[mf][nf][2], acc[mf][nf][3]);
            }
        }
    }
}

// ---------------- packed f32x2 helpers (FFMA2 kernels) ----------------------------
__device__ __forceinline__ void ffma2(unsigned long long& acc,
                                      unsigned long long a, unsigned long long b) {
    asm("fma.rn.f32x2 %0, %1, %2, %0;" : "+l"(acc) : "l"(a), "l"(b));
}
__device__ __forceinline__ unsigned long long pack2(float x, float y) {
    unsigned long long r;
    asm("mov.b64 %0, {%1, %2};" : "=l"(r) : "f"(x), "f"(y));
    return r;
}
__device__ __forceinline__ float2 unpack2(unsigned long long v) {
    float2 f;
    asm("mov.b64 {%0, %1}, %2;" : "=f"(f.x), "=f"(f.y) : "l"(v));
    return f;
}

// -------- fused masking + gather: every block recomputes ranks from noise --------
__global__ void maskgather_kernel(const float* __restrict__ noise,
                                  const float* __restrict__ pix,
                                  float* __restrict__ out_mask,
                                  float* __restrict__ out_ids) {
    __shared__ float s[NPATCH];
    __shared__ int p_sel;
    int m = blockIdx.x;
    int t = m % SEQL, b = m / SEQL;
    int tid = threadIdx.x;
    gdc_wait();
    if (tid < NPATCH) s[tid] = noise[b*NPATCH + tid];
    __syncthreads();
    int rank = -1;
    if (tid < NPATCH) {
        float v = s[tid];
        rank = 0;
        #pragma unroll 4
        for (int j = 0; j < NPATCH; j++) {
            float u = s[j];
            rank += (u < v) || (u == v && j < tid);
        }
    }
    if (t == 0) {
        if (tid < NPATCH) {
            out_mask[b*NPATCH + tid] = (rank >= LEN_KEEP) ? 1.0f : 0.0f;
            out_ids [b*NPATCH + tid] = (float)rank;
        }
        if (tid == 0) g_rowpatch[m] = -1;
        for (int k = tid; k < DM; k += blockDim.x) g_patches[m*DM + k] = 0.0f;
        return;
    }
    if (rank == t - 1) p_sel = tid;      // exactly one thread matches
    __syncthreads();
    int p = p_sel;
    if (tid == 0) g_rowpatch[m] = p;
    int pi = p / 14, pj = p % 14;
    for (int k = tid; k < DM; k += blockDim.x) {
        int c = k >> 8, rem = k & 255, r = rem >> 4, cc = rem & 15;
        g_patches[m*DM + k] =
            pix[((size_t)(b*3 + c)*224 + pi*16 + r)*224 + pj*16 + cc];
    }
}

// =============== FFMA2 SGEMM (patch-embed and dt) =================================
// EPI: 1 patch-embed | 2 softplus(+dt_bias)
template<int EPI>
__global__ __launch_bounds__(256)
void sgemm3(const float* __restrict__ A, const float* __restrict__ W,
            float* __restrict__ C, int M, int N, int K, int lda, int Klen,
            const float* __restrict__ ep0, const float* __restrict__ ep1,
            const float* __restrict__ ep2, const int* __restrict__ rowinfo) {
    constexpr int BM = 64, BN = 64, BK = 16;
    constexpr int PA = 132;
    constexpr int PB = 68;
    __shared__ __align__(16) float As2[2][BK][PA];
    __shared__ __align__(16) float Bs [2][BK][PB];
    const int tid = threadIdx.x;
    const int m0 = blockIdx.x * BM;
    const int n0 = blockIdx.y * BN;
    const int koff = blockIdx.z * Klen;
    const int tx = tid & 15;
    const int ty = tid >> 4;
    unsigned long long acc[4][2];
    #pragma unroll
    for (int i = 0; i < 4; i++) { acc[i][0] = 0ull; acc[i][1] = 0ull; }
    const int KT = Klen / BK;
    const int li = tid >> 4, lj = tid & 15;
    gdc_wait();
    #pragma unroll
    for (int r = 0; r < 4; r++) {
        int i = li + r*16;
        int gm = m0 + i;
        float va = (gm < M) ? A[(size_t)gm * lda + koff + lj] : 0.0f;
        *(unsigned long long*)&As2[0][lj][2*i] = pack2(va, va);
        Bs[0][lj][i] = W[(size_t)(n0 + i) * K + koff + lj];
    }
    __syncthreads();
    int s = 0;
    for (int kt = 0; kt < KT; kt++) {
        float ra[4], rb[4];
        if (kt + 1 < KT) {
            int k0 = koff + (kt + 1) * BK;
            #pragma unroll
            for (int r = 0; r < 4; r++) {
                int i = li + r*16;
                int gm = m0 + i;
                ra[r] = (gm < M) ? A[(size_t)gm * lda + k0 + lj] : 0.0f;
                rb[r] = W[(size_t)(n0 + i) * K + k0 + lj];
            }
        }
        #pragma unroll
        for (int kk = 0; kk < BK; kk++) {
            ulonglong2 a01 = *(const ulonglong2*)&As2[s][kk][ty*8];
            ulonglong2 a23 = *(const ulonglong2*)&As2[s][kk][ty*8 + 4];
            ulonglong2 bq  = *(const ulonglong2*)&Bs [s][kk][tx*4];
            ffma2(acc[0][0], a01.x, bq.x); ffma2(acc[0][1], a01.x, bq.y);
            ffma2(acc[1][0], a01.y, bq.x); ffma2(acc[1][1], a01.y, bq.y);
            ffma2(acc[2][0], a23.x, bq.x); ffma2(acc[2][1], a23.x, bq.y);
            ffma2(acc[3][0], a23.y, bq.x); ffma2(acc[3][1], a23.y, bq.y);
        }
        if (kt + 1 < KT) {
            int sn = s ^ 1;
            #pragma unroll
            for (int r = 0; r < 4; r++) {
                int i = li + r*16;
                *(unsigned long long*)&As2[sn][lj][2*i] = pack2(ra[r], ra[r]);
                Bs[sn][lj][i] = rb[r];
            }
            __syncthreads();
            s = sn;
        }
    }
    #pragma unroll
    for (int i = 0; i < 4; i++) {
        int m = m0 + ty*4 + i;
        if (m >= M) continue;
        int rp = 0;
        if (EPI == 1) rp = rowinfo[m];
        #pragma unroll
        for (int j = 0; j < 2; j++) {
            float2 v2 = unpack2(acc[i][j]);
            int n = n0 + tx*4 + j*2;
            if (EPI == 2) {
                float x0 = v2.x + ep0[n],   x1 = v2.y + ep0[n+1];
                v2.x = (x0 > 20.0f) ? x0 : log1pf(__expf(x0));
                v2.y = (x1 > 20.0f) ? x1 : log1pf(__expf(x1));
                *(float2*)&C[(size_t)m * N + n] = v2;
            } else { // EPI == 1
                float vv[2] = {v2.x, v2.y};
                #pragma unroll
                for (int q = 0; q < 2; q++) {
                    int nn = n + q;
                    float v = vv[q];
                    if (rp < 0) v = ep1[nn] + ep2[nn];
                    else        v = v + ep0[nn] + ep2[(size_t)(1+rp)*DM + nn];
                    C[(size_t)m * N + nn] = v;
                }
            }
        }
    }
}

// -------- xdbl SGEMM: BM=64 x BN=80 (full N), split-K, scalar RED epilogue --------
// No y-replication of the A (xc) read. TM=4 rows x TN=5 cols per thread.
__global__ __launch_bounds__(256)
void sgemm_xdbl(const float* __restrict__ A, const float* __restrict__ W,
                float* __restrict__ C, int M, int Klen) {
    constexpr int BM = 64, BN = 80, BK = 16;
    __shared__ float As[BK][BM + 4];
    __shared__ float Bs[BK][BN + 4];
    const int tid = threadIdx.x;
    const int m0 = blockIdx.x * BM;
    const int koff = blockIdx.z * Klen;
    const int tx = tid & 15;        // 16 threads x TN=5 = 80
    const int ty = tid >> 4;        // 16 threads x TM=4 = 64
    float acc[4][5];
    #pragma unroll
    for (int i = 0; i < 4; i++)
        #pragma unroll
        for (int j = 0; j < 5; j++) acc[i][j] = 0.0f;
    gdc_wait();
    for (int k0 = koff; k0 < koff + Klen; k0 += BK) {
        #pragma unroll
        for (int r = 0; r < 4; r++) {           // A: 64x16 = 1024 floats
            int idx = tid + r * 256;
            int i = idx >> 4, j = idx & 15;
            int gm = m0 + i;
            As[j][i] = (gm < M) ? A[(size_t)gm * DI + k0 + j] : 0.0f;
        }
        #pragma unroll
        for (int r = 0; r < 5; r++) {           // B: 80x16 = 1280 floats
            int idx = tid + r * 256;
            int i = idx >> 4, j = idx & 15;
            Bs[j][i] = W[(size_t)i * DI + k0 + j];
        }
        __syncthreads();
        #pragma unroll
        for (int kk = 0; kk < BK; kk++) {
            float a[4], bb[5];
            #pragma unroll
            for (int i = 0; i < 4; i++) a[i] = As[kk][ty*4 + i];
            #pragma unroll
            for (int j = 0; j < 5; j++) bb[j] = Bs[kk][tx*5 + j];
            #pragma unroll
            for (int i = 0; i < 4; i++)
                #pragma unroll
                for (int j = 0; j < 5; j++)
                    acc[i][j] = fmaf(a[i], bb[j], acc[i][j]);
        }
        __syncthreads();
    }
    #pragma unroll
    for (int i = 0; i < 4; i++) {
        int m = m0 + ty*4 + i;
        if (m >= M) continue;
        #pragma unroll
        for (int j = 0; j < 5; j++)
            red_add1(&C[(size_t)m * XDBLN + tx*5 + j], acc[i][j]);
    }
}

// ------- depthwise causal conv1d (k=4) + SiLU, 4 tokens/block, register window ---
// grid = BATCH * 37 (SEQL/4) = 296 blocks; also zero-inits the 4 xdbl rows.
__global__ void conv_silu_kernel(const float* __restrict__ cw,
                                 const float* __restrict__ cb) {
    const int blk = blockIdx.x;
    const int b  = blk / (SEQL/4);
    const int tg = blk % (SEQL/4);
    const int t0 = tg * 4;
    const int m0 = b*SEQL + t0;
    const int tid = threadIdx.x;
    gdc_wait();
    for (int i = tid; i < 4*XDBLN; i += 256)
        g_xdbl[(size_t)(m0 + i/XDBLN)*XDBLN + (i % XDBLN)] = 0.0f;
    const float* base = g_xz + (size_t)(b*SEQL) * (2*DI);
    #pragma unroll
    for (int k = 0; k < DI/256; k++) {            // 6 channels per thread
        int d = tid + k*256;
        float4 w = *(const float4*)&cw[d*4];
        float bias = cb[d];
        float win[7];
        #pragma unroll
        for (int j = 0; j < 7; j++) {
            int t = t0 - 3 + j;
            win[j] = (t >= 0) ? base[(size_t)t*(2*DI) + d] : 0.0f;
        }
        #pragma unroll
        for (int tt = 0; tt < 4; tt++) {
            float s = bias;
            s = fmaf(w.x, win[tt],     s);
            s = fmaf(w.y, win[tt + 1], s);
            s = fmaf(w.z, win[tt + 2], s);
            s = fmaf(w.w, win[tt + 3], s);
            float sig = 1.0f / (1.0f + __expf(-s));
            g_xc[(size_t)(m0 + tt)*DI + d] = s * sig;
        }
    }
}

// ---------------- layernorm (row per block, 256 threads, DM=768) -----------------
__device__ __forceinline__ float block_reduce_sum_256(float v, float* sh, float* bc) {
    #pragma unroll
    for (int o = 16; o > 0; o >>= 1) v += __shfl_xor_sync(0xffffffffu, v, o);
    int w = threadIdx.x >> 5;
    if ((threadIdx.x & 31) == 0) sh[w] = v;
    __syncthreads();
    if (threadIdx.x == 0) {
        float s = 0.0f;
        #pragma unroll
        for (int i = 0; i < 8; i++) s += sh[i];
        *bc = s;
    }
    __syncthreads();
    return *bc;
}

__global__ void ln_kernel(const float* __restrict__ x, const float* __restrict__ w,
                          const float* __restrict__ bias, float* __restrict__ out) {
    __shared__ float sh[8];
    __shared__ float bc;
    int m = blockIdx.x, tid = threadIdx.x;
    gdc_wait();
    const float* xr = x + (size_t)m * DM;
    float v0 = xr[tid], v1 = xr[tid + 256], v2 = xr[tid + 512];
    float mean = block_reduce_sum_256(v0 + v1 + v2, sh, &bc) * (1.0f / DM);
    float d0 = v0 - mean, d1 = v1 - mean, d2 = v2 - mean;
    __syncthreads();
    float var = block_reduce_sum_256(d0*d0 + d1*d1 + d2*d2, sh, &bc) * (1.0f / DM);
    float inv = rsqrtf(var + 1e-12f);
    float* o = out + (size_t)m * DM;
    o[tid]       = d0 * inv * w[tid]       + bias[tid];
    o[tid + 256] = d1 * inv * w[tid + 256] + bias[tid + 256];
    o[tid + 512] = d2 * inv * w[tid + 512] + bias[tid + 512];
}

// ---------------- selective scan: 16 lanes/channel, prefetched loads --------------
__global__ void scan_kernel(const float* __restrict__ A_log_l,
                            const float* __restrict__ Dp_l) {
    int lane = threadIdx.x & 31;
    int warp = threadIdx.x >> 5;
    int widx = blockIdx.x * 8 + warp;
    int ch = widx * 2 + (lane >> 4);       // 2 channels per warp
    int b = ch / DI, d = ch % DI;
    int n = lane & 15;
    // independent preamble (reads immutable inputs only)
    float Av = -__expf(A_log_l[d*DSTATE + n]);
    float Dv = Dp_l[d];
    float h = 0.0f;
    int base = b * SEQL;
    gdc_wait();
    float dt = g_dt[(size_t)base*DI + d];
    float xc = g_xc[(size_t)base*DI + d];
    float Bn = g_xdbl[(size_t)base*XDBLN + DTR + n];
    float Cn = g_xdbl[(size_t)base*XDBLN + DTR + DSTATE + n];
    for (int t = 0; t < SEQL; t++) {
        float dtN, xcN, BnN, CnN;
        if (t + 1 < SEQL) {
            int m1 = base + t + 1;
            dtN = g_dt[(size_t)m1*DI + d];
            xcN = g_xc[(size_t)m1*DI + d];
            BnN = g_xdbl[(size_t)m1*XDBLN + DTR + n];
            CnN = g_xdbl[(size_t)m1*XDBLN + DTR + DSTATE + n];
        }
        float dA = __expf(dt * Av);
        h = fmaf(dA, h, (dt * xc) * Bn);
        float p = h * Cn;
        p += __shfl_xor_sync(0xffffffffu, p, 8);
        p += __shfl_xor_sync(0xffffffffu, p, 4);
        p += __shfl_xor_sync(0xffffffffu, p, 2);
        p += __shfl_xor_sync(0xffffffffu, p, 1);
        if (n == 0) {
            int m = base + t;
            float z = g_xz[(size_t)m*(2*DI) + DI + d];
            float y = (p + xc * Dv) * (z / (1.0f + __expf(-z)));
            g_y[(size_t)m*DI + d] = y;
        }
        dt = dtN; xc = xcN; Bn = BnN; Cn = CnN;
    }
}

// ---------------- PDL launch helper ------------------------------------------------
template<typename K, typename... Args>
static inline void launchP(K kern, dim3 g, dim3 b, Args... args) {
    cudaLaunchConfig_t cfg = {};
    cfg.gridDim = g;
    cfg.blockDim = b;
    cfg.dynamicSmemBytes = 0;
    cudaLaunchAttribute attrs[1];
    attrs[0].id = cudaLaunchAttributeProgrammaticStreamSerialization;
    attrs[0].val.programmaticStreamSerializationAllowed = 1;
    cfg.attrs = attrs;
    cfg.numAttrs = 1;
    cudaLaunchKernelEx(&cfg, kern, args...);
}

// ---------------- host launcher ---------------------------------------------------
extern "C" void kernel_launch(void* const* d_in, const int* in_sizes, int n_in,
                              void* d_out, int out_size) {
    const float* pixel     = (const float*)d_in[0];
    const float* noise     = (const float*)d_in[1];
    const float* conv_w    = (const float*)d_in[2];
    const float* conv_b    = (const float*)d_in[3];
    const float* cls_token = (const float*)d_in[4];
    const float* pos_embed = (const float*)d_in[5];
    const float* ln_w      = (const float*)d_in[6];
    const float* ln_b      = (const float*)d_in[7];
    const float* W_in      = (const float*)d_in[8];
    const float* conv1d_w  = (const float*)d_in[9];
    const float* conv1d_b  = (const float*)d_in[10];
    const float* W_x       = (const float*)d_in[11];
    const float* W_dt      = (const float*)d_in[12];
    const float* dt_bias   = (const float*)d_in[13];
    const float* A_log     = (const float*)d_in[14];
    const float* Dp        = (const float*)d_in[15];
    const float* W_out     = (const float*)d_in[16];
    const float* lnf_w     = (const float*)d_in[17];
    const float* lnf_b     = (const float*)d_in[18];

    float* out      = (float*)d_out;
    float* out_h    = out;                       // (8,148,768)
    float* out_mask = out + (size_t)MROWS*DM;    // (8,196)
    float* out_ids  = out_mask + BATCH*NPATCH;   // (8,196) as float

    float *p_patches, *p_h, *p_ln, *p_xz, *p_xc, *p_xdbl, *p_dt, *p_y;
    int *p_rowpatch;
    cudaGetSymbolAddress((void**)&p_patches, g_patches);
    cudaGetSymbolAddress((void**)&p_h,       g_h);
    cudaGetSymbolAddress((void**)&p_ln,      g_ln);
    cudaGetSymbolAddress((void**)&p_xz,      g_xz);
    cudaGetSymbolAddress((void**)&p_xc,      g_xc);
    cudaGetSymbolAddress((void**)&p_xdbl,    g_xdbl);
    cudaGetSymbolAddress((void**)&p_dt,      g_dt);
    cudaGetSymbolAddress((void**)&p_y,       g_y);
    cudaGetSymbolAddress((void**)&p_rowpatch, g_rowpatch);

    const int MB64  = (MROWS + 63) / 64;     // 19
    const int MB128 = (MROWS + 127) / 128;   // 10

    // fused masking + patch gather, then patch-embed GEMM (both PDL-chained)
    launchP(maskgather_kernel, dim3(MROWS), dim3(256),
            noise, pixel, out_mask, out_ids);
    launchP(sgemm3<1>, dim3(MB64, DM/64, 1), dim3(256),
            (const float*)p_patches, conv_w, p_h,
            MROWS, DM, DM, DM, DM, conv_b, cls_token, pos_embed,
            (const int*)p_rowpatch);

    for (int l = 0; l < NLAYERS; l++) {
        const float* Wi  = W_in     + (size_t)l * (2*DI) * DM;
        const float* cw  = conv1d_w + (size_t)l * DI * 4;
        const float* cb  = conv1d_b + (size_t)l * DI;
        const float* Wx  = W_x      + (size_t)l * XDBLN * DI;
        const float* Wd  = W_dt     + (size_t)l * DI * DTR;
        const float* db  = dt_bias  + (size_t)l * DI;
        const float* Al  = A_log    + (size_t)l * DI * DSTATE;
        const float* Dl  = Dp       + (size_t)l * DI;
        const float* Wo  = W_out    + (size_t)l * DM * DI;

        // layernorm
        launchP(ln_kernel, dim3(MROWS), dim3(256),
                (const float*)p_h, ln_w + l*DM, ln_b + l*DM, p_ln);

        // xz = ln @ W_in^T — bf16x3 tensor GEMM
        launchP(mma_bf16x3<0>, dim3(MB128, (2*DI)/128, 1), dim3(256),
                (const float*)p_ln, Wi, p_xz, MROWS, 2*DI, DM, DM, DM);

        // depthwise causal conv + silu (4 tokens/block; zero-inits xdbl rows)
        launchP(conv_silu_kernel, dim3(BATCH * (SEQL/4)), dim3(256), cw, cb);

        // x_dbl = xc @ W_x^T — BN=80, split-K=8, scalar RED
        launchP(sgemm_xdbl, dim3(MB64, 1, 8), dim3(256),
                (const float*)p_xc, Wx, p_xdbl, MROWS, DI/8);

        // dt = softplus(x_dbl[:, :48] @ W_dt^T + dt_bias)
        launchP(sgemm3<2>, dim3(MB64, DI/64, 1), dim3(256),
                (const float*)p_xdbl, Wd, p_dt,
                MROWS, DI, DTR, XDBLN, DTR, db,
                (const float*)nullptr, (const float*)nullptr,
                (const int*)nullptr);

        // selective scan + D skip + gate
        launchP(scan_kernel, dim3((BATCH*DI)/16), dim3(256), Al, Dl);

        // h += y @ W_out^T — bf16x3 split-K=4, vector RED accumulate
        launchP(mma_bf16x3<1>, dim3(MB128, DM/128, 4), dim3(256),
                (const float*)p_y, Wo, p_h, MROWS, DM, DI, DI, DI/4);
    }

    // final layernorm straight into the output buffer
    launchP(ln_kernel, dim3(MROWS), dim3(256),
            (const float*)p_h, lnf_w, lnf_b, out_h);
}